// round 2
// baseline (speedup 1.0000x reference)
#include <cuda_runtime.h>

#define NB 16
#define NA 512
#define NH 8
#define HD 32
#define HIDDEN 256

// Scratch for projected Q/K/V (static __device__ arrays: allocation-guard safe)
__device__ float g_q[NB * NA * HIDDEN];
__device__ float g_k[NB * NA * HIDDEN];
__device__ float g_v[NB * NA * HIDDEN];

// ---------------------------------------------------------------------------
// QKV projection: out[r][j] = sum_k x[r][k] * W[j][k]   (y = x @ W^T)
// rows = NB*NA = 8192, cols = 256. blockIdx.z selects Wq/Wk/Wv.
// 64x64 output tile per CTA, 256 threads, 4x4 microtile, K-chunks of 16.
// ---------------------------------------------------------------------------
__global__ __launch_bounds__(256) void qkv_kernel(
    const float* __restrict__ x, const float* __restrict__ Wq,
    const float* __restrict__ Wk, const float* __restrict__ Wv)
{
    __shared__ float sA[16 * 68];   // [c][r], stride 68 for bank spread + f4 align
    __shared__ float sB[16 * 68];

    const float* W;
    float* out;
    if (blockIdx.z == 0)      { W = Wq; out = g_q; }
    else if (blockIdx.z == 1) { W = Wk; out = g_k; }
    else                      { W = Wv; out = g_v; }

    const int row0 = blockIdx.y * 64;
    const int col0 = blockIdx.x * 64;
    const int t  = threadIdx.x;
    const int ty = t >> 4;          // 0..15 -> 4 output rows each
    const int tx = t & 15;          // 0..15 -> 4 output cols each
    const int lr = t >> 2;          // load row 0..63
    const int lc = (t & 3) * 4;     // load col base 0,4,8,12

    float acc[4][4] = {};

    for (int k0 = 0; k0 < HIDDEN; k0 += 16) {
        float4 a = *(const float4*)(x + (row0 + lr) * HIDDEN + k0 + lc);
        float4 w = *(const float4*)(W + (col0 + lr) * HIDDEN + k0 + lc);
        sA[(lc + 0) * 68 + lr] = a.x;
        sA[(lc + 1) * 68 + lr] = a.y;
        sA[(lc + 2) * 68 + lr] = a.z;
        sA[(lc + 3) * 68 + lr] = a.w;
        sB[(lc + 0) * 68 + lr] = w.x;
        sB[(lc + 1) * 68 + lr] = w.y;
        sB[(lc + 2) * 68 + lr] = w.z;
        sB[(lc + 3) * 68 + lr] = w.w;
        __syncthreads();

        #pragma unroll
        for (int c = 0; c < 16; c++) {
            float4 av = *(const float4*)(sA + c * 68 + ty * 4);
            float4 bv = *(const float4*)(sB + c * 68 + tx * 4);
            float aa[4] = {av.x, av.y, av.z, av.w};
            float bb[4] = {bv.x, bv.y, bv.z, bv.w};
            #pragma unroll
            for (int i = 0; i < 4; i++)
                #pragma unroll
                for (int j = 0; j < 4; j++)
                    acc[i][j] = fmaf(aa[i], bb[j], acc[i][j]);
        }
        __syncthreads();
    }

    #pragma unroll
    for (int i = 0; i < 4; i++) {
        float4 o = make_float4(acc[i][0], acc[i][1], acc[i][2], acc[i][3]);
        *(float4*)(out + (row0 + ty * 4 + i) * HIDDEN + col0 + tx * 4) = o;
    }
}

// ---------------------------------------------------------------------------
// Fused attention. CTA = (q_block of 64, head, batch). 256 threads.
// Full 64x512 score row kept in smem -> one-shot softmax (no online rescale).
//   S = QK^T / 8 + adj ; masked -> -1e30 ; softmax ; O = P V ; out = O + x
// smem: sQ[64][33] + sKV[64][33] + sS[64][512] = 147,968 B  (occ 1)
// ---------------------------------------------------------------------------
__global__ __launch_bounds__(256) void attn_kernel(
    const float* __restrict__ x, const int* __restrict__ mask,
    const float* __restrict__ adj, float* __restrict__ out)
{
    extern __shared__ float sm[];
    float* sQ  = sm;                 // [64][33]
    float* sKV = sm + 64 * 33;       // [64][33]  (K tiles, then V tiles)
    float* sS  = sm + 2 * 64 * 33;   // [64][512]

    const int qb = blockIdx.x, h = blockIdx.y, b = blockIdx.z;
    const int q0 = qb * 64;
    const int t  = threadIdx.x;
    const int ty = t >> 4;           // 0..15
    const int tx = t & 15;           // 0..15

    // Load Q block (64 rows x 32 dims of this head)
    for (int i = t; i < 64 * HD; i += 256) {
        int r = i >> 5, d = i & 31;
        sQ[r * 33 + d] = g_q[(b * NA + q0 + r) * HIDDEN + h * HD + d];
    }

    // ---- Phase 1: scores for all 8 K-tiles ----
    for (int kt = 0; kt < 8; kt++) {
        __syncthreads();  // sKV free of readers; also fences sQ load on iter 0
        for (int i = t; i < 64 * HD; i += 256) {
            int r = i >> 5, d = i & 31;
            sKV[r * 33 + d] = g_k[(b * NA + kt * 64 + r) * HIDDEN + h * HD + d];
        }
        __syncthreads();

        float accS[4][4] = {};
        #pragma unroll 8
        for (int d = 0; d < HD; d++) {
            float qv[4], kv[4];
            #pragma unroll
            for (int i = 0; i < 4; i++) qv[i] = sQ[(ty * 4 + i) * 33 + d];
            #pragma unroll
            for (int j = 0; j < 4; j++) kv[j] = sKV[(tx * 4 + j) * 33 + d];
            #pragma unroll
            for (int i = 0; i < 4; i++)
                #pragma unroll
                for (int j = 0; j < 4; j++)
                    accS[i][j] = fmaf(qv[i], kv[j], accS[i][j]);
        }

        #pragma unroll
        for (int i = 0; i < 4; i++) {
            int q = q0 + ty * 4 + i;
            #pragma unroll
            for (int j = 0; j < 4; j++) {
                int k = kt * 64 + tx * 4 + j;
                int idx = (b * NA + q) * NA + k;      // adj/mask: [b][q][k]
                float s = accS[i][j] * 0.125f + adj[idx];
                if (mask[idx] != 0) s = -1e30f;       // jax bool serialized as int32
                sS[(ty * 4 + i) * 512 + k] = s;
            }
        }
    }
    __syncthreads();

    // ---- Phase 2: row softmax (warp w owns rows 8w..8w+7) ----
    {
        int w = t >> 5, lane = t & 31;
        for (int r = w * 8; r < w * 8 + 8; r++) {
            float* row = sS + r * 512;
            float m = -1e30f;
            for (int c = lane; c < 512; c += 32) m = fmaxf(m, row[c]);
            #pragma unroll
            for (int o = 16; o > 0; o >>= 1)
                m = fmaxf(m, __shfl_xor_sync(0xffffffffu, m, o));
            float sum = 0.f;
            for (int c = lane; c < 512; c += 32) {
                float e = __expf(row[c] - m);
                row[c] = e;
                sum += e;
            }
            #pragma unroll
            for (int o = 16; o > 0; o >>= 1)
                sum += __shfl_xor_sync(0xffffffffu, sum, o);
            float inv = 1.0f / sum;
            for (int c = lane; c < 512; c += 32) row[c] *= inv;
        }
    }

    // ---- Phase 3: O = P @ V  (thread: 4 q-rows x 2 d-cols) ----
    float accO[4][2] = {};
    for (int kt = 0; kt < 8; kt++) {
        __syncthreads();  // prior kk-loop readers of sKV done; also fences phase 2
        for (int i = t; i < 64 * HD; i += 256) {
            int r = i >> 5, d = i & 31;
            sKV[r * 33 + d] = g_v[(b * NA + kt * 64 + r) * HIDDEN + h * HD + d];
        }
        __syncthreads();

        #pragma unroll 4
        for (int kk = 0; kk < 64; kk++) {
            float p[4];
            #pragma unroll
            for (int i = 0; i < 4; i++) p[i] = sS[(ty * 4 + i) * 512 + kt * 64 + kk];
            float v0 = sKV[kk * 33 + tx * 2];
            float v1 = sKV[kk * 33 + tx * 2 + 1];
            #pragma unroll
            for (int i = 0; i < 4; i++) {
                accO[i][0] = fmaf(p[i], v0, accO[i][0]);
                accO[i][1] = fmaf(p[i], v1, accO[i][1]);
            }
        }
    }

    // ---- Phase 4: out = O + x ----
    #pragma unroll
    for (int i = 0; i < 4; i++) {
        int gidx = (b * NA + q0 + ty * 4 + i) * HIDDEN + h * HD + tx * 2;
        float2 xv = *(const float2*)(x + gidx);
        float2 o;
        o.x = accO[i][0] + xv.x;
        o.y = accO[i][1] + xv.y;
        *(float2*)(out + gidx) = o;
    }
}

// ---------------------------------------------------------------------------
extern "C" void kernel_launch(void* const* d_in, const int* in_sizes, int n_in,
                              void* d_out, int out_size)
{
    const float* x    = (const float*)d_in[0];
    const int*   mask = (const int*)d_in[1];    // jax bool -> int32 in harness
    const float* adj  = (const float*)d_in[2];
    const float* Wq   = (const float*)d_in[3];
    const float* Wk   = (const float*)d_in[4];
    const float* Wv   = (const float*)d_in[5];
    float*       out  = (float*)d_out;

    // 1) Q/K/V projections into __device__ scratch
    qkv_kernel<<<dim3(4, 128, 3), 256>>>(x, Wq, Wk, Wv);

    // 2) Fused attention + residual
    const size_t smem = (size_t)(2 * 64 * 33 + 64 * 512) * sizeof(float); // 147,968 B
    cudaFuncSetAttribute(attn_kernel,
                         cudaFuncAttributeMaxDynamicSharedMemorySize, (int)smem);
    attn_kernel<<<dim3(NA / 64, NH, NB), 256, smem>>>(x, mask, adj, out);
}

// round 3
// speedup vs baseline: 1.6362x; 1.6362x over previous
#include <cuda_runtime.h>

#define NB 16
#define NA 512
#define NH 8
#define HD 32
#define HIDDEN 256

// Scratch for projected Q/K/V (static __device__ arrays: allocation-guard safe)
__device__ float g_q[NB * NA * HIDDEN];
__device__ float g_k[NB * NA * HIDDEN];
__device__ float g_v[NB * NA * HIDDEN];

// ---------------------------------------------------------------------------
// QKV projection: out[r][j] = sum_k x[r][k] * W[j][k]   (y = x @ W^T)
// ---------------------------------------------------------------------------
__global__ __launch_bounds__(256) void qkv_kernel(
    const float* __restrict__ x, const float* __restrict__ Wq,
    const float* __restrict__ Wk, const float* __restrict__ Wv)
{
    __shared__ float sA[16 * 68];
    __shared__ float sB[16 * 68];

    const float* W;
    float* out;
    if (blockIdx.z == 0)      { W = Wq; out = g_q; }
    else if (blockIdx.z == 1) { W = Wk; out = g_k; }
    else                      { W = Wv; out = g_v; }

    const int row0 = blockIdx.y * 64;
    const int col0 = blockIdx.x * 64;
    const int t  = threadIdx.x;
    const int ty = t >> 4;
    const int tx = t & 15;
    const int lr = t >> 2;
    const int lc = (t & 3) * 4;

    float acc[4][4] = {};

    for (int k0 = 0; k0 < HIDDEN; k0 += 16) {
        float4 a = *(const float4*)(x + (row0 + lr) * HIDDEN + k0 + lc);
        float4 w = *(const float4*)(W + (col0 + lr) * HIDDEN + k0 + lc);
        sA[(lc + 0) * 68 + lr] = a.x;
        sA[(lc + 1) * 68 + lr] = a.y;
        sA[(lc + 2) * 68 + lr] = a.z;
        sA[(lc + 3) * 68 + lr] = a.w;
        sB[(lc + 0) * 68 + lr] = w.x;
        sB[(lc + 1) * 68 + lr] = w.y;
        sB[(lc + 2) * 68 + lr] = w.z;
        sB[(lc + 3) * 68 + lr] = w.w;
        __syncthreads();

        #pragma unroll
        for (int c = 0; c < 16; c++) {
            float4 av = *(const float4*)(sA + c * 68 + ty * 4);
            float4 bv = *(const float4*)(sB + c * 68 + tx * 4);
            float aa[4] = {av.x, av.y, av.z, av.w};
            float bb[4] = {bv.x, bv.y, bv.z, bv.w};
            #pragma unroll
            for (int i = 0; i < 4; i++)
                #pragma unroll
                for (int j = 0; j < 4; j++)
                    acc[i][j] = fmaf(aa[i], bb[j], acc[i][j]);
        }
        __syncthreads();
    }

    #pragma unroll
    for (int i = 0; i < 4; i++) {
        float4 o = make_float4(acc[i][0], acc[i][1], acc[i][2], acc[i][3]);
        *(float4*)(out + (row0 + ty * 4 + i) * HIDDEN + col0 + tx * 4) = o;
    }
}

// ---------------------------------------------------------------------------
// Flash-style fused attention. CTA = (q_block 64, head, batch), 256 threads.
// Online softmax: no full score buffer. Smem 40KB -> 3 CTAs/SM.
// Thread (ty,tx): S microtile = q-rows ty*4..+3 x k-cols tx*4..+3.
//                 O microtile = q-rows ty*4..+3 x d-cols tx*2..+1.
// sK swizzled for conflict-free f4 reads along d; sV stored transposed
// (d-major) + swizzled for conflict-free f4 reads along kk.
// ---------------------------------------------------------------------------
__global__ __launch_bounds__(256, 3) void attn_kernel(
    const float* __restrict__ x, const int* __restrict__ mask,
    const float* __restrict__ adj, float* __restrict__ out)
{
    __shared__ float sQ [64 * 32];   // [r][d]       plain (reads are broadcast)
    __shared__ float sK [64 * 32];   // [r][d4^(r>>2)&7]  swizzled chunks
    __shared__ float sVT[32 * 64];   // [d][kk4^(d>>1)&15] transposed+swizzled
    __shared__ float sP [64 * 64];   // [r][kk]      plain (reads broadcast)

    const int h = blockIdx.y, b = blockIdx.z;
    const int q0 = blockIdx.x * 64;
    const int t  = threadIdx.x;
    const int ty = t >> 4;
    const int tx = t & 15;

    // Load Q block: 512 float4 chunks, 2 per thread
    {
        int cc = t;
        #pragma unroll
        for (int rep = 0; rep < 2; rep++, cc += 256) {
            int r = cc >> 3, c = cc & 7;
            float4 v = *(const float4*)(g_q + (size_t)(b * NA + q0 + r) * HIDDEN + h * HD + c * 4);
            *(float4*)(sQ + r * 32 + c * 4) = v;
        }
    }

    float m[4], l[4];
    float accO[4][2] = {};
    #pragma unroll
    for (int i = 0; i < 4; i++) { m[i] = -1e30f; l[i] = 0.f; }

    for (int kt = 0; kt < 8; kt++) {
        __syncthreads();   // prev iteration's readers of sK/sVT done (iter0: sQ fence)
        // ---- load K (swizzled) + V (transposed, swizzled) ----
        {
            int cc = t;
            #pragma unroll
            for (int rep = 0; rep < 2; rep++, cc += 256) {
                int r = cc >> 3, c = cc & 7;
                const size_t g = (size_t)(b * NA + kt * 64 + r) * HIDDEN + h * HD + c * 4;
                float4 kv = *(const float4*)(g_k + g);
                *(float4*)(sK + r * 32 + ((c ^ ((r >> 2) & 7)) << 2)) = kv;
                float4 vv = *(const float4*)(g_v + g);
                float ve[4] = {vv.x, vv.y, vv.z, vv.w};
                #pragma unroll
                for (int e = 0; e < 4; e++) {
                    int d = c * 4 + e;
                    sVT[d * 64 + (((r >> 2) ^ ((d >> 1) & 15)) << 2) + (r & 3)] = ve[e];
                }
            }
        }
        __syncthreads();

        // ---- S = Q K^T (64x64 tile, 4x4 microtile, f4 along d) ----
        float accS[4][4] = {};
        #pragma unroll
        for (int d4 = 0; d4 < 8; d4++) {
            float4 q4[4];
            #pragma unroll
            for (int i = 0; i < 4; i++)
                q4[i] = *(const float4*)(sQ + (ty * 4 + i) * 32 + d4 * 4);
            #pragma unroll
            for (int j = 0; j < 4; j++) {
                float4 k4 = *(const float4*)(sK + (tx * 4 + j) * 32 + ((d4 ^ (tx & 7)) << 2));
                #pragma unroll
                for (int i = 0; i < 4; i++) {
                    accS[i][j] = fmaf(q4[i].x, k4.x, accS[i][j]);
                    accS[i][j] = fmaf(q4[i].y, k4.y, accS[i][j]);
                    accS[i][j] = fmaf(q4[i].z, k4.z, accS[i][j]);
                    accS[i][j] = fmaf(q4[i].w, k4.w, accS[i][j]);
                }
            }
        }

        // ---- epilogue: adj + mask + online softmax; write P ----
        #pragma unroll
        for (int i = 0; i < 4; i++) {
            const int q = q0 + ty * 4 + i;
            const size_t base = (size_t)(b * NA + q) * NA + kt * 64 + tx * 4;
            float4 a4 = *(const float4*)(adj + base);
            int4  mk4 = *(const int4*)(mask + base);
            float s0 = fmaf(accS[i][0], 0.125f, a4.x); if (mk4.x) s0 = -1e30f;
            float s1 = fmaf(accS[i][1], 0.125f, a4.y); if (mk4.y) s1 = -1e30f;
            float s2 = fmaf(accS[i][2], 0.125f, a4.z); if (mk4.z) s2 = -1e30f;
            float s3 = fmaf(accS[i][3], 0.125f, a4.w); if (mk4.w) s3 = -1e30f;

            float rmax = fmaxf(fmaxf(s0, s1), fmaxf(s2, s3));
            #pragma unroll
            for (int o = 8; o > 0; o >>= 1)
                rmax = fmaxf(rmax, __shfl_xor_sync(0xffffffffu, rmax, o));

            float mn   = fmaxf(m[i], rmax);
            float corr = __expf(m[i] - mn);
            float p0 = __expf(s0 - mn);
            float p1 = __expf(s1 - mn);
            float p2 = __expf(s2 - mn);
            float p3 = __expf(s3 - mn);
            float rsum = (p0 + p1) + (p2 + p3);
            #pragma unroll
            for (int o = 8; o > 0; o >>= 1)
                rsum += __shfl_xor_sync(0xffffffffu, rsum, o);

            l[i] = l[i] * corr + rsum;
            m[i] = mn;
            accO[i][0] *= corr;
            accO[i][1] *= corr;
            *(float4*)(sP + (ty * 4 + i) * 64 + tx * 4) = make_float4(p0, p1, p2, p3);
        }
        // sP row r is written and read by the SAME half-warp (ty group) -> warp sync only
        __syncwarp();

        // ---- O += P V (f4 along kk) ----
        #pragma unroll 4
        for (int kk4 = 0; kk4 < 16; kk4++) {
            float4 p4[4];
            #pragma unroll
            for (int i = 0; i < 4; i++)
                p4[i] = *(const float4*)(sP + (ty * 4 + i) * 64 + kk4 * 4);
            float4 va = *(const float4*)(sVT + (2 * tx)     * 64 + ((kk4 ^ tx) << 2));
            float4 vb = *(const float4*)(sVT + (2 * tx + 1) * 64 + ((kk4 ^ tx) << 2));
            #pragma unroll
            for (int i = 0; i < 4; i++) {
                accO[i][0] = fmaf(p4[i].x, va.x, accO[i][0]);
                accO[i][0] = fmaf(p4[i].y, va.y, accO[i][0]);
                accO[i][0] = fmaf(p4[i].z, va.z, accO[i][0]);
                accO[i][0] = fmaf(p4[i].w, va.w, accO[i][0]);
                accO[i][1] = fmaf(p4[i].x, vb.x, accO[i][1]);
                accO[i][1] = fmaf(p4[i].y, vb.y, accO[i][1]);
                accO[i][1] = fmaf(p4[i].z, vb.z, accO[i][1]);
                accO[i][1] = fmaf(p4[i].w, vb.w, accO[i][1]);
            }
        }
    }

    // ---- finalize: /l, residual, store ----
    #pragma unroll
    for (int i = 0; i < 4; i++) {
        float inv = 1.0f / l[i];
        size_t g = (size_t)(b * NA + q0 + ty * 4 + i) * HIDDEN + h * HD + tx * 2;
        float2 xv = *(const float2*)(x + g);
        float2 o;
        o.x = fmaf(accO[i][0], inv, xv.x);
        o.y = fmaf(accO[i][1], inv, xv.y);
        *(float2*)(out + g) = o;
    }
}

// ---------------------------------------------------------------------------
extern "C" void kernel_launch(void* const* d_in, const int* in_sizes, int n_in,
                              void* d_out, int out_size)
{
    const float* x    = (const float*)d_in[0];
    const int*   mask = (const int*)d_in[1];    // jax bool -> int32 in harness
    const float* adj  = (const float*)d_in[2];
    const float* Wq   = (const float*)d_in[3];
    const float* Wk   = (const float*)d_in[4];
    const float* Wv   = (const float*)d_in[5];
    float*       out  = (float*)d_out;

    qkv_kernel<<<dim3(4, 128, 3), 256>>>(x, Wq, Wk, Wv);
    attn_kernel<<<dim3(NA / 64, NH, NB), 256>>>(x, mask, adj, out);
}

// round 5
// speedup vs baseline: 2.2999x; 1.4056x over previous
#include <cuda_runtime.h>
#include <cuda_bf16.h>
#include <cstdint>

#define NB 16
#define NA 512
#define NH 8
#define HD 32
#define HIDDEN 256

// bf16 hi/lo split Q/K/V, [row][hidden], produced by qkv kernel. 0=Q 1=K 2=V.
__device__ __nv_bfloat16 g_hi[3][NB * NA * HIDDEN];
__device__ __nv_bfloat16 g_lo[3][NB * NA * HIDDEN];

// ---------------------------------------------------------------------------
// helpers
// ---------------------------------------------------------------------------
__device__ __forceinline__ uint32_t smem_u32(const void* p) {
    uint32_t a;
    asm("{ .reg .u64 t; cvta.to.shared.u64 t, %1; cvt.u32.u64 %0, t; }" : "=r"(a) : "l"(p));
    return a;
}
__device__ __forceinline__ void ldsm_x4(uint32_t* r, uint32_t a) {
    asm volatile("ldmatrix.sync.aligned.m8n8.x4.shared.b16 {%0,%1,%2,%3}, [%4];"
                 : "=r"(r[0]), "=r"(r[1]), "=r"(r[2]), "=r"(r[3]) : "r"(a));
}
__device__ __forceinline__ void ldsm_x2(uint32_t& r0, uint32_t& r1, uint32_t a) {
    asm volatile("ldmatrix.sync.aligned.m8n8.x2.shared.b16 {%0,%1}, [%2];"
                 : "=r"(r0), "=r"(r1) : "r"(a));
}
__device__ __forceinline__ void ldsm_x2t(uint32_t& r0, uint32_t& r1, uint32_t a) {
    asm volatile("ldmatrix.sync.aligned.m8n8.x2.trans.shared.b16 {%0,%1}, [%2];"
                 : "=r"(r0), "=r"(r1) : "r"(a));
}
__device__ __forceinline__ void mma16816(float* c, const uint32_t* a, uint32_t b0, uint32_t b1) {
    asm volatile("mma.sync.aligned.m16n8k16.row.col.f32.bf16.bf16.f32 "
                 "{%0,%1,%2,%3}, {%4,%5,%6,%7}, {%8,%9}, {%0,%1,%2,%3};"
                 : "+f"(c[0]), "+f"(c[1]), "+f"(c[2]), "+f"(c[3])
                 : "r"(a[0]), "r"(a[1]), "r"(a[2]), "r"(a[3]), "r"(b0), "r"(b1));
}
// pack two fp32 -> bf16x2 (lo -> bits[15:0], hi -> bits[31:16])
__device__ __forceinline__ uint32_t packbf(float lo, float hi) {
    uint32_t r;
    asm("cvt.rn.bf16x2.f32 %0, %1, %2;" : "=r"(r) : "f"(hi), "f"(lo));
    return r;
}
__device__ __forceinline__ unsigned short bf_bits(float v) {
    __nv_bfloat16 h = __float2bfloat16(v);
    return *reinterpret_cast<unsigned short*>(&h);
}

// ---------------------------------------------------------------------------
// QKV projection (FFMA) with bf16 hi/lo split epilogue. z selects Q/K/V.
// ---------------------------------------------------------------------------
__global__ __launch_bounds__(256) void qkv_kernel(
    const float* __restrict__ x, const float* __restrict__ Wq,
    const float* __restrict__ Wk, const float* __restrict__ Wv)
{
    __shared__ float sA[16 * 68];
    __shared__ float sB[16 * 68];

    const float* W;
    if (blockIdx.z == 0)      W = Wq;
    else if (blockIdx.z == 1) W = Wk;
    else                      W = Wv;

    const int row0 = blockIdx.y * 64;
    const int col0 = blockIdx.x * 64;
    const int t  = threadIdx.x;
    const int ty = t >> 4;
    const int tx = t & 15;
    const int lr = t >> 2;
    const int lc = (t & 3) * 4;

    float acc[4][4] = {};

    for (int k0 = 0; k0 < HIDDEN; k0 += 16) {
        float4 a = *(const float4*)(x + (row0 + lr) * HIDDEN + k0 + lc);
        float4 w = *(const float4*)(W + (col0 + lr) * HIDDEN + k0 + lc);
        sA[(lc + 0) * 68 + lr] = a.x;  sA[(lc + 1) * 68 + lr] = a.y;
        sA[(lc + 2) * 68 + lr] = a.z;  sA[(lc + 3) * 68 + lr] = a.w;
        sB[(lc + 0) * 68 + lr] = w.x;  sB[(lc + 1) * 68 + lr] = w.y;
        sB[(lc + 2) * 68 + lr] = w.z;  sB[(lc + 3) * 68 + lr] = w.w;
        __syncthreads();
        #pragma unroll
        for (int c = 0; c < 16; c++) {
            float4 av = *(const float4*)(sA + c * 68 + ty * 4);
            float4 bv = *(const float4*)(sB + c * 68 + tx * 4);
            float aa[4] = {av.x, av.y, av.z, av.w};
            float bb[4] = {bv.x, bv.y, bv.z, bv.w};
            #pragma unroll
            for (int i = 0; i < 4; i++)
                #pragma unroll
                for (int j = 0; j < 4; j++)
                    acc[i][j] = fmaf(aa[i], bb[j], acc[i][j]);
        }
        __syncthreads();
    }

    __nv_bfloat16* ohi = g_hi[blockIdx.z];
    __nv_bfloat16* olo = g_lo[blockIdx.z];
    #pragma unroll
    for (int i = 0; i < 4; i++) {
        unsigned short hb[4], lb[4];
        #pragma unroll
        for (int j = 0; j < 4; j++) {
            float v = acc[i][j];
            __nv_bfloat16 h = __float2bfloat16(v);
            hb[j] = *reinterpret_cast<unsigned short*>(&h);
            lb[j] = bf_bits(v - __bfloat162float(h));
        }
        size_t o = (size_t)(row0 + ty * 4 + i) * HIDDEN + col0 + tx * 4;
        *(ushort4*)(ohi + o) = make_ushort4(hb[0], hb[1], hb[2], hb[3]);
        *(ushort4*)(olo + o) = make_ushort4(lb[0], lb[1], lb[2], lb[3]);
    }
}

// ---------------------------------------------------------------------------
// FA2-style attention on mma.sync bf16 (3-term hi/lo split).
// CTA = (q-block 128, head, batch), 8 warps; warp owns 16 q-rows.
// Smem rows padded to 144B (hi 64B | lo 64B | pad 16B) -> LDSM conflict-free.
// ---------------------------------------------------------------------------
#define OQ 0                     // 128 * 144 = 18432
#define OK 18432                 // 64 * 144  = 9216
#define OV 27648                 // 64 * 144  = 9216
#define SMT 36864

__global__ __launch_bounds__(256, 2) void attn_kernel(
    const float* __restrict__ x, const int* __restrict__ mask,
    const float* __restrict__ adj, float* __restrict__ out)
{
    __shared__ __align__(16) unsigned char sm[SMT];
    const uint32_t sb = smem_u32(sm);

    const int tid  = threadIdx.x;
    const int w    = tid >> 5;
    const int lane = tid & 31;
    const int l4   = lane & 15;
    const int qd   = lane & 3;           // quad position (cols)
    const int b = blockIdx.z, h = blockIdx.y;
    const int q0 = blockIdx.x * 128;

    const __nv_bfloat16* Qh = g_hi[0];
    const __nv_bfloat16* Ql = g_lo[0];
    const __nv_bfloat16* Kh = g_hi[1];
    const __nv_bfloat16* Kl = g_lo[1];
    const __nv_bfloat16* Vh = g_hi[2];
    const __nv_bfloat16* Vl = g_lo[2];

    // ---- stage Q (128 rows x (64B hi | 64B lo)) ----
    #pragma unroll
    for (int i = 0; i < 4; i++) {
        int idx = i * 256 + tid;
        int r = idx >> 3, c = idx & 7;
        size_t g = (size_t)(b * NA + q0 + r) * HIDDEN + h * HD;
        uint4 v = (c < 4) ? ((const uint4*)(Qh + g))[c] : ((const uint4*)(Ql + g))[c - 4];
        *(uint4*)(sm + OQ + r * 144 + c * 16) = v;
    }
    __syncthreads();

    // ---- preload Q A-fragments: qf[p(hi/lo)][s(k16 step)][4] ----
    uint32_t qf[2][2][4];
    {
        uint32_t base = sb + OQ + (16 * w + l4) * 144 + ((lane >> 4) & 1) * 16;
        #pragma unroll
        for (int p = 0; p < 2; p++)
            #pragma unroll
            for (int s = 0; s < 2; s++)
                ldsm_x4(qf[p][s], base + p * 64 + s * 32);
    }

    float m0 = -1e30f, m1 = -1e30f, l0 = 0.f, l1 = 0.f;
    float oacc[4][4] = {};                // 4 n8 d-tiles

    const int qg0 = q0 + 16 * w + (lane >> 2);   // this thread's row0 (row1 = +8)

    for (int kt = 0; kt < 8; kt++) {
        __syncthreads();
        // ---- stage K, V tiles (64 rows each) ----
        #pragma unroll
        for (int i = 0; i < 2; i++) {
            int idx = i * 256 + tid;
            int r = idx >> 3, c = idx & 7;
            size_t g = (size_t)(b * NA + kt * 64 + r) * HIDDEN + h * HD;
            uint4 kv = (c < 4) ? ((const uint4*)(Kh + g))[c] : ((const uint4*)(Kl + g))[c - 4];
            *(uint4*)(sm + OK + r * 144 + c * 16) = kv;
            uint4 vv = (c < 4) ? ((const uint4*)(Vh + g))[c] : ((const uint4*)(Vl + g))[c - 4];
            *(uint4*)(sm + OV + r * 144 + c * 16) = vv;
        }
        __syncthreads();

        // ---- S = QK^T : 3 split terms x 2 k16 steps x 8 n8 tiles ----
        float sacc[8][4];
        #pragma unroll
        for (int j = 0; j < 8; j++)
            #pragma unroll
            for (int e = 0; e < 4; e++) sacc[j][e] = 0.f;

        #pragma unroll
        for (int t3 = 0; t3 < 3; t3++) {
            const int pq = (t3 == 1) ? 1 : 0;    // Qlo only in term 1
            const int pk = (t3 == 2) ? 1 : 0;    // Klo only in term 2
            #pragma unroll
            for (int s = 0; s < 2; s++) {
                uint32_t kbase = sb + OK + (l4 & 7) * 144 + pk * 64 + s * 32 + ((l4 >> 3) & 1) * 16;
                #pragma unroll
                for (int j = 0; j < 8; j++) {
                    uint32_t b0, b1;
                    ldsm_x2(b0, b1, kbase + j * (8 * 144));
                    mma16816(sacc[j], qf[pq][s], b0, b1);
                }
            }
        }

        // ---- adj + mask + row max ----
        const size_t arow0 = ((size_t)b * NA + qg0) * NA + kt * 64 + qd * 2;
        float rmax0 = -1e30f, rmax1 = -1e30f;
        #pragma unroll
        for (int j = 0; j < 8; j++) {
            float2 a0 = *(const float2*)(adj + arow0 + 8 * j);
            float2 a1 = *(const float2*)(adj + arow0 + 8 * NA + 8 * j);
            int2  mk0 = *(const int2*)(mask + arow0 + 8 * j);
            int2  mk1 = *(const int2*)(mask + arow0 + 8 * NA + 8 * j);
            float s0 = fmaf(sacc[j][0], 0.125f, a0.x); if (mk0.x) s0 = -1e30f;
            float s1 = fmaf(sacc[j][1], 0.125f, a0.y); if (mk0.y) s1 = -1e30f;
            float s2 = fmaf(sacc[j][2], 0.125f, a1.x); if (mk1.x) s2 = -1e30f;
            float s3 = fmaf(sacc[j][3], 0.125f, a1.y); if (mk1.y) s3 = -1e30f;
            sacc[j][0] = s0; sacc[j][1] = s1; sacc[j][2] = s2; sacc[j][3] = s3;
            rmax0 = fmaxf(rmax0, fmaxf(s0, s1));
            rmax1 = fmaxf(rmax1, fmaxf(s2, s3));
        }
        #pragma unroll
        for (int o = 1; o <= 2; o <<= 1) {
            rmax0 = fmaxf(rmax0, __shfl_xor_sync(0xffffffffu, rmax0, o));
            rmax1 = fmaxf(rmax1, __shfl_xor_sync(0xffffffffu, rmax1, o));
        }

        const float mn0 = fmaxf(m0, rmax0), mn1 = fmaxf(m1, rmax1);
        const float corr0 = __expf(m0 - mn0), corr1 = __expf(m1 - mn1);
        m0 = mn0; m1 = mn1;

        // ---- exp, split, pack P into A-fragments pf[p][k16 step][4] ----
        uint32_t pf[2][4][4];
        float sum0 = 0.f, sum1 = 0.f;
        #pragma unroll
        for (int jp = 0; jp < 4; jp++) {
            float pv[2][4];   // [which n8 of the pair][elem]
            #pragma unroll
            for (int half = 0; half < 2; half++) {
                int j = 2 * jp + half;
                float p0 = __expf(sacc[j][0] - mn0);
                float p1 = __expf(sacc[j][1] - mn0);
                float p2 = __expf(sacc[j][2] - mn1);
                float p3 = __expf(sacc[j][3] - mn1);
                sum0 += p0 + p1; sum1 += p2 + p3;
                pv[half][0] = p0; pv[half][1] = p1; pv[half][2] = p2; pv[half][3] = p3;
            }
            #pragma unroll
            for (int half = 0; half < 2; half++) {
                float h0 = __bfloat162float(__float2bfloat16(pv[half][0]));
                float h1 = __bfloat162float(__float2bfloat16(pv[half][1]));
                float h2 = __bfloat162float(__float2bfloat16(pv[half][2]));
                float h3 = __bfloat162float(__float2bfloat16(pv[half][3]));
                pf[0][jp][2 * half + 0] = packbf(h0, h1);
                pf[0][jp][2 * half + 1] = packbf(h2, h3);
                pf[1][jp][2 * half + 0] = packbf(pv[half][0] - h0, pv[half][1] - h1);
                pf[1][jp][2 * half + 1] = packbf(pv[half][2] - h2, pv[half][3] - h3);
            }
        }
        #pragma unroll
        for (int o = 1; o <= 2; o <<= 1) {
            sum0 += __shfl_xor_sync(0xffffffffu, sum0, o);
            sum1 += __shfl_xor_sync(0xffffffffu, sum1, o);
        }
        l0 = l0 * corr0 + sum0;
        l1 = l1 * corr1 + sum1;

        // ---- rescale O, then O += P V (3 terms x 4 k16 x 4 n8) ----
        #pragma unroll
        for (int j = 0; j < 4; j++) {
            oacc[j][0] *= corr0; oacc[j][1] *= corr0;
            oacc[j][2] *= corr1; oacc[j][3] *= corr1;
        }
        #pragma unroll
        for (int t3 = 0; t3 < 3; t3++) {
            const int ph = (t3 == 2) ? 1 : 0;    // Plo only in term 2
            const int pv_ = (t3 == 1) ? 1 : 0;   // Vlo only in term 1
            #pragma unroll
            for (int s2 = 0; s2 < 4; s2++) {
                uint32_t vbase = sb + OV + (16 * s2 + l4) * 144 + pv_ * 64;
                #pragma unroll
                for (int j = 0; j < 4; j++) {
                    uint32_t b0, b1;
                    ldsm_x2t(b0, b1, vbase + j * 16);
                    mma16816(oacc[j], pf[ph][s2], b0, b1);
                }
            }
        }
    }

    // ---- finalize: /l + residual ----
    {
        const float inv0 = 1.0f / l0, inv1 = 1.0f / l1;
        const size_t g0 = ((size_t)b * NA + qg0) * HIDDEN + h * HD + qd * 2;
        #pragma unroll
        for (int j = 0; j < 4; j++) {
            float2 x0 = *(const float2*)(x + g0 + 8 * j);
            float2 x1 = *(const float2*)(x + g0 + 8 * HIDDEN + 8 * j);
            float2 o0, o1;
            o0.x = fmaf(oacc[j][0], inv0, x0.x);
            o0.y = fmaf(oacc[j][1], inv0, x0.y);
            o1.x = fmaf(oacc[j][2], inv1, x1.x);
            o1.y = fmaf(oacc[j][3], inv1, x1.y);
            *(float2*)(out + g0 + 8 * j) = o0;
            *(float2*)(out + g0 + 8 * HIDDEN + 8 * j) = o1;
        }
    }
}

// ---------------------------------------------------------------------------
extern "C" void kernel_launch(void* const* d_in, const int* in_sizes, int n_in,
                              void* d_out, int out_size)
{
    const float* x    = (const float*)d_in[0];
    const int*   mask = (const int*)d_in[1];    // jax bool -> int32 in harness
    const float* adj  = (const float*)d_in[2];
    const float* Wq   = (const float*)d_in[3];
    const float* Wk   = (const float*)d_in[4];
    const float* Wv   = (const float*)d_in[5];
    float*       out  = (float*)d_out;

    qkv_kernel<<<dim3(4, 128, 3), 256>>>(x, Wq, Wk, Wv);
    attn_kernel<<<dim3(NA / 128, NH, NB), 256>>>(x, mask, adj, out);
}

// round 6
// speedup vs baseline: 2.5327x; 1.1012x over previous
#include <cuda_runtime.h>
#include <cuda_bf16.h>
#include <cstdint>

#define NB 16
#define NA 512
#define NH 8
#define HD 32
#define HIDDEN 256

// bf16 hi/lo split Q/K/V, [row][hidden], produced by qkv kernel. 0=Q 1=K 2=V.
__device__ __nv_bfloat16 g_hi[3][NB * NA * HIDDEN];
__device__ __nv_bfloat16 g_lo[3][NB * NA * HIDDEN];
// combined adjacency+mask: mask ? -1e30 : adj
__device__ float g_adjm[NB * NA * NA];

// ---------------------------------------------------------------------------
// helpers
// ---------------------------------------------------------------------------
__device__ __forceinline__ uint32_t smem_u32(const void* p) {
    uint32_t a;
    asm("{ .reg .u64 t; cvta.to.shared.u64 t, %1; cvt.u32.u64 %0, t; }" : "=r"(a) : "l"(p));
    return a;
}
__device__ __forceinline__ void ldsm_x4(uint32_t* r, uint32_t a) {
    asm volatile("ldmatrix.sync.aligned.m8n8.x4.shared.b16 {%0,%1,%2,%3}, [%4];"
                 : "=r"(r[0]), "=r"(r[1]), "=r"(r[2]), "=r"(r[3]) : "r"(a));
}
__device__ __forceinline__ void ldsm_x2(uint32_t& r0, uint32_t& r1, uint32_t a) {
    asm volatile("ldmatrix.sync.aligned.m8n8.x2.shared.b16 {%0,%1}, [%2];"
                 : "=r"(r0), "=r"(r1) : "r"(a));
}
__device__ __forceinline__ void ldsm_x2t(uint32_t& r0, uint32_t& r1, uint32_t a) {
    asm volatile("ldmatrix.sync.aligned.m8n8.x2.trans.shared.b16 {%0,%1}, [%2];"
                 : "=r"(r0), "=r"(r1) : "r"(a));
}
__device__ __forceinline__ void mma16816(float* c, const uint32_t* a, uint32_t b0, uint32_t b1) {
    asm volatile("mma.sync.aligned.m16n8k16.row.col.f32.bf16.bf16.f32 "
                 "{%0,%1,%2,%3}, {%4,%5,%6,%7}, {%8,%9}, {%0,%1,%2,%3};"
                 : "+f"(c[0]), "+f"(c[1]), "+f"(c[2]), "+f"(c[3])
                 : "r"(a[0]), "r"(a[1]), "r"(a[2]), "r"(a[3]), "r"(b0), "r"(b1));
}
__device__ __forceinline__ void cp16(uint32_t s, const void* g) {
    asm volatile("cp.async.cg.shared.global [%0], [%1], 16;" :: "r"(s), "l"(g));
}
#define CP_COMMIT() asm volatile("cp.async.commit_group;" ::: "memory")
#define CP_WAIT0()  asm volatile("cp.async.wait_group 0;" ::: "memory")

__device__ __forceinline__ uint32_t packbf(float lo, float hi) {
    uint32_t r;
    asm("cvt.rn.bf16x2.f32 %0, %1, %2;" : "=r"(r) : "f"(hi), "f"(lo));
    return r;
}
__device__ __forceinline__ unsigned short bf_bits(float v) {
    __nv_bfloat16 h = __float2bfloat16(v);
    return *reinterpret_cast<unsigned short*>(&h);
}

// ---------------------------------------------------------------------------
// adjm = mask ? -1e30 : adj   (one-shot bandwidth kernel)
// ---------------------------------------------------------------------------
__global__ __launch_bounds__(256) void adjm_kernel(
    const float* __restrict__ adj, const int* __restrict__ mask)
{
    size_t i = ((size_t)blockIdx.x * 256 + threadIdx.x) * 4;
    float4 a = *(const float4*)(adj + i);
    int4   m = *(const int4*)(mask + i);
    if (m.x) a.x = -1e30f;
    if (m.y) a.y = -1e30f;
    if (m.z) a.z = -1e30f;
    if (m.w) a.w = -1e30f;
    *(float4*)(g_adjm + i) = a;
}

// ---------------------------------------------------------------------------
// QKV projection (FFMA) with bf16 hi/lo split epilogue. z selects Q/K/V.
// ---------------------------------------------------------------------------
__global__ __launch_bounds__(256) void qkv_kernel(
    const float* __restrict__ x, const float* __restrict__ Wq,
    const float* __restrict__ Wk, const float* __restrict__ Wv)
{
    __shared__ float sA[16 * 68];
    __shared__ float sB[16 * 68];

    const float* W;
    if (blockIdx.z == 0)      W = Wq;
    else if (blockIdx.z == 1) W = Wk;
    else                      W = Wv;

    const int row0 = blockIdx.y * 64;
    const int col0 = blockIdx.x * 64;
    const int t  = threadIdx.x;
    const int ty = t >> 4;
    const int tx = t & 15;
    const int lr = t >> 2;
    const int lc = (t & 3) * 4;

    float acc[4][4] = {};

    for (int k0 = 0; k0 < HIDDEN; k0 += 16) {
        float4 a = *(const float4*)(x + (row0 + lr) * HIDDEN + k0 + lc);
        float4 w = *(const float4*)(W + (col0 + lr) * HIDDEN + k0 + lc);
        sA[(lc + 0) * 68 + lr] = a.x;  sA[(lc + 1) * 68 + lr] = a.y;
        sA[(lc + 2) * 68 + lr] = a.z;  sA[(lc + 3) * 68 + lr] = a.w;
        sB[(lc + 0) * 68 + lr] = w.x;  sB[(lc + 1) * 68 + lr] = w.y;
        sB[(lc + 2) * 68 + lr] = w.z;  sB[(lc + 3) * 68 + lr] = w.w;
        __syncthreads();
        #pragma unroll
        for (int c = 0; c < 16; c++) {
            float4 av = *(const float4*)(sA + c * 68 + ty * 4);
            float4 bv = *(const float4*)(sB + c * 68 + tx * 4);
            float aa[4] = {av.x, av.y, av.z, av.w};
            float bb[4] = {bv.x, bv.y, bv.z, bv.w};
            #pragma unroll
            for (int i = 0; i < 4; i++)
                #pragma unroll
                for (int j = 0; j < 4; j++)
                    acc[i][j] = fmaf(aa[i], bb[j], acc[i][j]);
        }
        __syncthreads();
    }

    __nv_bfloat16* ohi = g_hi[blockIdx.z];
    __nv_bfloat16* olo = g_lo[blockIdx.z];
    #pragma unroll
    for (int i = 0; i < 4; i++) {
        unsigned short hb[4], lb[4];
        #pragma unroll
        for (int j = 0; j < 4; j++) {
            float v = acc[i][j];
            __nv_bfloat16 h = __float2bfloat16(v);
            hb[j] = *reinterpret_cast<unsigned short*>(&h);
            lb[j] = bf_bits(v - __bfloat162float(h));
        }
        size_t o = (size_t)(row0 + ty * 4 + i) * HIDDEN + col0 + tx * 4;
        *(ushort4*)(ohi + o) = make_ushort4(hb[0], hb[1], hb[2], hb[3]);
        *(ushort4*)(olo + o) = make_ushort4(lb[0], lb[1], lb[2], lb[3]);
    }
}

// ---------------------------------------------------------------------------
// FA2-style attention, cp.async pipelined.
// CTA = (q-block 128, head, batch), 8 warps; warp owns 16 q-rows.
// Smem (dynamic, 86KB): Q 18432 | KV double buf 2x18432 | adjm 32768.
// K/V rows 144B (hi 64 | lo 64 | pad 16); adjm rows 256B, 16B-chunk XOR swizzle.
// ---------------------------------------------------------------------------
#define OQ    0
#define OKV0  18432
#define OKV1  36864
#define OADJ  55296
#define SMT   88064
#define KVOFS 9216            // V offset within a KV buffer

__global__ __launch_bounds__(256, 2) void attn_kernel(
    const float* __restrict__ x, float* __restrict__ out)
{
    extern __shared__ __align__(16) unsigned char sm[];
    const uint32_t sb = smem_u32(sm);

    const int tid  = threadIdx.x;
    const int w    = tid >> 5;
    const int lane = tid & 31;
    const int l4   = lane & 15;
    const int qd   = lane & 3;
    const int b = blockIdx.z, h = blockIdx.y;
    const int q0 = blockIdx.x * 128;

    const __nv_bfloat16* Qh = g_hi[0];
    const __nv_bfloat16* Ql = g_lo[0];
    const __nv_bfloat16* Kh = g_hi[1];
    const __nv_bfloat16* Kl = g_lo[1];
    const __nv_bfloat16* Vh = g_hi[2];
    const __nv_bfloat16* Vl = g_lo[2];

    // ---- staging helpers (256 threads each call) ----
    auto stage_kv = [&](int kt, uint32_t obuf) {
        #pragma unroll
        for (int i = 0; i < 4; i++) {
            int idx = i * 256 + tid;          // 0..1023
            int isV = idx >> 9;               // 0:K 1:V
            int r   = (idx >> 3) & 63;
            int c   = idx & 7;
            size_t g = (size_t)(b * NA + kt * 64 + r) * HIDDEN + h * HD;
            const __nv_bfloat16* hi = isV ? Vh : Kh;
            const __nv_bfloat16* lo = isV ? Vl : Kl;
            const char* src = (c < 4) ? (const char*)(hi + g) + c * 16
                                      : (const char*)(lo + g) + (c - 4) * 16;
            cp16(sb + obuf + isV * KVOFS + r * 144 + c * 16, src);
        }
    };
    auto stage_adjm = [&](int kt) {
        #pragma unroll
        for (int i = 0; i < 8; i++) {
            int idx = i * 256 + tid;          // 0..2047
            int r   = idx >> 4;               // 0..127
            int c16 = idx & 15;
            int pc  = c16 ^ (2 * (r & 7));    // XOR swizzle on 16B chunks
            const float* src = g_adjm + ((size_t)(b * NA + q0 + r)) * NA + kt * 64 + c16 * 4;
            cp16(sb + OADJ + r * 256 + pc * 16, src);
        }
    };

    // ---- stage Q (regular stores) ----
    #pragma unroll
    for (int i = 0; i < 4; i++) {
        int idx = i * 256 + tid;
        int r = idx >> 3, c = idx & 7;
        size_t g = (size_t)(b * NA + q0 + r) * HIDDEN + h * HD;
        uint4 v = (c < 4) ? ((const uint4*)(Qh + g))[c] : ((const uint4*)(Ql + g))[c - 4];
        *(uint4*)(sm + OQ + r * 144 + c * 16) = v;
    }
    // ---- prefetch tile 0 ----
    stage_kv(0, OKV0);
    CP_COMMIT();
    stage_adjm(0);
    CP_COMMIT();
    __syncthreads();   // Q visible

    // ---- preload Q A-fragments: qf[p(hi/lo)][s(k16 step)][4] ----
    uint32_t qf[2][2][4];
    {
        uint32_t base = sb + OQ + (16 * w + l4) * 144 + ((lane >> 4) & 1) * 16;
        #pragma unroll
        for (int p = 0; p < 2; p++)
            #pragma unroll
            for (int s = 0; s < 2; s++)
                ldsm_x4(qf[p][s], base + p * 64 + s * 32);
    }

    float m0 = -1e30f, m1 = -1e30f, l0 = 0.f, l1 = 0.f;
    float oacc[4][4] = {};

    const int rw = 16 * w + (lane >> 2);          // q-row (0..127) within block
    const int r7 = rw & 7;

    for (int kt = 0; kt < 8; kt++) {
        const uint32_t obuf = (kt & 1) ? OKV1 : OKV0;
        CP_WAIT0();
        __syncthreads();                           // KV[kt] + adjm[kt] visible

        // ---- S = QK^T : 3 split terms x 2 k16 steps x 8 n8 tiles ----
        float sacc[8][4];
        #pragma unroll
        for (int j = 0; j < 8; j++)
            #pragma unroll
            for (int e = 0; e < 4; e++) sacc[j][e] = 0.f;

        #pragma unroll
        for (int t3 = 0; t3 < 3; t3++) {
            const int pq = (t3 == 1) ? 1 : 0;
            const int pk = (t3 == 2) ? 1 : 0;
            #pragma unroll
            for (int s = 0; s < 2; s++) {
                uint32_t kbase = sb + obuf + (l4 & 7) * 144 + pk * 64 + s * 32 + ((l4 >> 3) & 1) * 16;
                #pragma unroll
                for (int j = 0; j < 8; j++) {
                    uint32_t b0, b1;
                    ldsm_x2(b0, b1, kbase + j * (8 * 144));
                    mma16816(sacc[j], qf[pq][s], b0, b1);
                }
            }
        }

        // ---- scores from smem adjm (masked entries already -1e30) ----
        const uint32_t arow = sb + OADJ + rw * 256;
        float rmax0 = -1e30f, rmax1 = -1e30f;
        #pragma unroll
        for (int j = 0; j < 8; j++) {
            uint32_t off = (uint32_t)(((qd + 4 * j) ^ (4 * r7)) << 3);
            float2 a0 = *(const float2*)(sm + (arow - sb) + off);
            float2 a1 = *(const float2*)(sm + (arow - sb) + 8 * 256 + off);
            float s0 = fmaf(sacc[j][0], 0.125f, a0.x);
            float s1 = fmaf(sacc[j][1], 0.125f, a0.y);
            float s2 = fmaf(sacc[j][2], 0.125f, a1.x);
            float s3 = fmaf(sacc[j][3], 0.125f, a1.y);
            sacc[j][0] = s0; sacc[j][1] = s1; sacc[j][2] = s2; sacc[j][3] = s3;
            rmax0 = fmaxf(rmax0, fmaxf(s0, s1));
            rmax1 = fmaxf(rmax1, fmaxf(s2, s3));
        }
        #pragma unroll
        for (int o = 1; o <= 2; o <<= 1) {
            rmax0 = fmaxf(rmax0, __shfl_xor_sync(0xffffffffu, rmax0, o));
            rmax1 = fmaxf(rmax1, __shfl_xor_sync(0xffffffffu, rmax1, o));
        }

        const float mn0 = fmaxf(m0, rmax0), mn1 = fmaxf(m1, rmax1);
        const float corr0 = __expf(m0 - mn0), corr1 = __expf(m1 - mn1);
        m0 = mn0; m1 = mn1;

        // ---- exp, split, pack P fragments pf[p][k16 step][4] ----
        uint32_t pf[2][4][4];
        float sum0 = 0.f, sum1 = 0.f;
        #pragma unroll
        for (int jp = 0; jp < 4; jp++) {
            float pv[2][4];
            #pragma unroll
            for (int half = 0; half < 2; half++) {
                int j = 2 * jp + half;
                float p0 = __expf(sacc[j][0] - mn0);
                float p1 = __expf(sacc[j][1] - mn0);
                float p2 = __expf(sacc[j][2] - mn1);
                float p3 = __expf(sacc[j][3] - mn1);
                sum0 += p0 + p1; sum1 += p2 + p3;
                pv[half][0] = p0; pv[half][1] = p1; pv[half][2] = p2; pv[half][3] = p3;
            }
            #pragma unroll
            for (int half = 0; half < 2; half++) {
                float h0 = __bfloat162float(__float2bfloat16(pv[half][0]));
                float h1 = __bfloat162float(__float2bfloat16(pv[half][1]));
                float h2 = __bfloat162float(__float2bfloat16(pv[half][2]));
                float h3 = __bfloat162float(__float2bfloat16(pv[half][3]));
                pf[0][jp][2 * half + 0] = packbf(h0, h1);
                pf[0][jp][2 * half + 1] = packbf(h2, h3);
                pf[1][jp][2 * half + 0] = packbf(pv[half][0] - h0, pv[half][1] - h1);
                pf[1][jp][2 * half + 1] = packbf(pv[half][2] - h2, pv[half][3] - h3);
            }
        }
        #pragma unroll
        for (int o = 1; o <= 2; o <<= 1) {
            sum0 += __shfl_xor_sync(0xffffffffu, sum0, o);
            sum1 += __shfl_xor_sync(0xffffffffu, sum1, o);
        }
        l0 = l0 * corr0 + sum0;
        l1 = l1 * corr1 + sum1;

        // ---- adjm consumed by all -> prefetch next tile ----
        __syncthreads();
        if (kt < 7) {
            stage_kv(kt + 1, (kt & 1) ? OKV0 : OKV1);
            CP_COMMIT();
            stage_adjm(kt + 1);
            CP_COMMIT();
        }

        // ---- rescale O, then O += P V (3 terms x 4 k16 x 4 n8) ----
        #pragma unroll
        for (int j = 0; j < 4; j++) {
            oacc[j][0] *= corr0; oacc[j][1] *= corr0;
            oacc[j][2] *= corr1; oacc[j][3] *= corr1;
        }
        #pragma unroll
        for (int t3 = 0; t3 < 3; t3++) {
            const int ph  = (t3 == 2) ? 1 : 0;
            const int pv_ = (t3 == 1) ? 1 : 0;
            #pragma unroll
            for (int s2 = 0; s2 < 4; s2++) {
                uint32_t vbase = sb + obuf + KVOFS + (16 * s2 + l4) * 144 + pv_ * 64;
                #pragma unroll
                for (int j = 0; j < 4; j++) {
                    uint32_t b0, b1;
                    ldsm_x2t(b0, b1, vbase + j * 16);
                    mma16816(oacc[j], pf[ph][s2], b0, b1);
                }
            }
        }
    }

    // ---- finalize: /l + residual ----
    {
        const float inv0 = 1.0f / l0, inv1 = 1.0f / l1;
        const size_t g0 = ((size_t)b * NA + q0 + rw) * HIDDEN + h * HD + qd * 2;
        #pragma unroll
        for (int j = 0; j < 4; j++) {
            float2 x0 = *(const float2*)(x + g0 + 8 * j);
            float2 x1 = *(const float2*)(x + g0 + 8 * HIDDEN + 8 * j);
            float2 o0, o1;
            o0.x = fmaf(oacc[j][0], inv0, x0.x);
            o0.y = fmaf(oacc[j][1], inv0, x0.y);
            o1.x = fmaf(oacc[j][2], inv1, x1.x);
            o1.y = fmaf(oacc[j][3], inv1, x1.y);
            *(float2*)(out + g0 + 8 * j) = o0;
            *(float2*)(out + g0 + 8 * HIDDEN + 8 * j) = o1;
        }
    }
}

// ---------------------------------------------------------------------------
extern "C" void kernel_launch(void* const* d_in, const int* in_sizes, int n_in,
                              void* d_out, int out_size)
{
    const float* x    = (const float*)d_in[0];
    const int*   mask = (const int*)d_in[1];    // jax bool -> int32 in harness
    const float* adj  = (const float*)d_in[2];
    const float* Wq   = (const float*)d_in[3];
    const float* Wk   = (const float*)d_in[4];
    const float* Wv   = (const float*)d_in[5];
    float*       out  = (float*)d_out;

    adjm_kernel<<<NB * NA * NA / 1024, 256>>>(adj, mask);
    qkv_kernel<<<dim3(4, 128, 3), 256>>>(x, Wq, Wk, Wv);

    cudaFuncSetAttribute(attn_kernel,
                         cudaFuncAttributeMaxDynamicSharedMemorySize, SMT);
    attn_kernel<<<dim3(NA / 128, NH, NB), 256, SMT>>>(x, out);
}

// round 7
// speedup vs baseline: 3.5512x; 1.4021x over previous
#include <cuda_runtime.h>
#include <cuda_bf16.h>
#include <cstdint>

#define NB 16
#define NA 512
#define NH 8
#define HD 32
#define HIDDEN 256

// bf16 hi/lo split Q/K/V, [row][hidden]. 0=Q 1=K 2=V.
__device__ __nv_bfloat16 g_hi[3][NB * NA * HIDDEN];
__device__ __nv_bfloat16 g_lo[3][NB * NA * HIDDEN];
// combined adjacency+mask: mask ? -1e30 : adj
__device__ float g_adjm[NB * NA * NA];
// bf16 hi/lo split of x and the three weight matrices
__device__ __nv_bfloat16 g_xh[NB * NA * HIDDEN];
__device__ __nv_bfloat16 g_xl[NB * NA * HIDDEN];
__device__ __nv_bfloat16 g_wh[3][HIDDEN * HIDDEN];
__device__ __nv_bfloat16 g_wl[3][HIDDEN * HIDDEN];

// ---------------------------------------------------------------------------
// helpers
// ---------------------------------------------------------------------------
__device__ __forceinline__ uint32_t smem_u32(const void* p) {
    uint32_t a;
    asm("{ .reg .u64 t; cvta.to.shared.u64 t, %1; cvt.u32.u64 %0, t; }" : "=r"(a) : "l"(p));
    return a;
}
__device__ __forceinline__ void ldsm_x4(uint32_t* r, uint32_t a) {
    asm volatile("ldmatrix.sync.aligned.m8n8.x4.shared.b16 {%0,%1,%2,%3}, [%4];"
                 : "=r"(r[0]), "=r"(r[1]), "=r"(r[2]), "=r"(r[3]) : "r"(a));
}
__device__ __forceinline__ void ldsm_x2(uint32_t& r0, uint32_t& r1, uint32_t a) {
    asm volatile("ldmatrix.sync.aligned.m8n8.x2.shared.b16 {%0,%1}, [%2];"
                 : "=r"(r0), "=r"(r1) : "r"(a));
}
__device__ __forceinline__ void ldsm_x2t(uint32_t& r0, uint32_t& r1, uint32_t a) {
    asm volatile("ldmatrix.sync.aligned.m8n8.x2.trans.shared.b16 {%0,%1}, [%2];"
                 : "=r"(r0), "=r"(r1) : "r"(a));
}
__device__ __forceinline__ void mma16816(float* c, const uint32_t* a, uint32_t b0, uint32_t b1) {
    asm volatile("mma.sync.aligned.m16n8k16.row.col.f32.bf16.bf16.f32 "
                 "{%0,%1,%2,%3}, {%4,%5,%6,%7}, {%8,%9}, {%0,%1,%2,%3};"
                 : "+f"(c[0]), "+f"(c[1]), "+f"(c[2]), "+f"(c[3])
                 : "r"(a[0]), "r"(a[1]), "r"(a[2]), "r"(a[3]), "r"(b0), "r"(b1));
}
__device__ __forceinline__ void cp16(uint32_t s, const void* g) {
    asm volatile("cp.async.cg.shared.global [%0], [%1], 16;" :: "r"(s), "l"(g));
}
#define CP_COMMIT() asm volatile("cp.async.commit_group;" ::: "memory")
#define CP_WAIT0()  asm volatile("cp.async.wait_group 0;" ::: "memory")

// pack (a -> bits[15:0], b -> bits[31:16])
__device__ __forceinline__ uint32_t packbf(float a, float b) {
    uint32_t r;
    asm("cvt.rn.bf16x2.f32 %0, %1, %2;" : "=r"(r) : "f"(b), "f"(a));
    return r;
}

// ---------------------------------------------------------------------------
// prepro: adjm = mask ? -1e30 : adj
// ---------------------------------------------------------------------------
__global__ __launch_bounds__(256) void adjm_kernel(
    const float* __restrict__ adj, const int* __restrict__ mask)
{
    size_t i = ((size_t)blockIdx.x * 256 + threadIdx.x) * 4;
    float4 a = *(const float4*)(adj + i);
    int4   m = *(const int4*)(mask + i);
    if (m.x) a.x = -1e30f;
    if (m.y) a.y = -1e30f;
    if (m.z) a.z = -1e30f;
    if (m.w) a.w = -1e30f;
    *(float4*)(g_adjm + i) = a;
}

// ---------------------------------------------------------------------------
// prepro: fp32 -> bf16 hi/lo split (x and W)
// ---------------------------------------------------------------------------
__device__ __forceinline__ void split4(const float* src, __nv_bfloat16* dh,
                                       __nv_bfloat16* dl, size_t i)
{
    float4 v = *(const float4*)(src + i);
    uint32_t h0 = packbf(v.x, v.y);
    uint32_t h1 = packbf(v.z, v.w);
    float f0 = __uint_as_float(h0 << 16);
    float f1 = __uint_as_float(h0 & 0xFFFF0000u);
    float f2 = __uint_as_float(h1 << 16);
    float f3 = __uint_as_float(h1 & 0xFFFF0000u);
    uint32_t l0 = packbf(v.x - f0, v.y - f1);
    uint32_t l1 = packbf(v.z - f2, v.w - f3);
    *(uint2*)(dh + i) = make_uint2(h0, h1);
    *(uint2*)(dl + i) = make_uint2(l0, l1);
}
__global__ __launch_bounds__(256) void xsplit_kernel(const float* __restrict__ x)
{
    size_t i = ((size_t)blockIdx.x * 256 + threadIdx.x) * 4;
    split4(x, g_xh, g_xl, i);
}
__global__ __launch_bounds__(256) void wsplit_kernel(
    const float* __restrict__ Wq, const float* __restrict__ Wk,
    const float* __restrict__ Wv)
{
    const int z = blockIdx.y;
    const float* W = (z == 0) ? Wq : (z == 1) ? Wk : Wv;
    size_t i = ((size_t)blockIdx.x * 256 + threadIdx.x) * 4;
    split4(W, g_wh[z], g_wl[z], i);
}

// ---------------------------------------------------------------------------
// QKV projection on HMMA: out = x @ W^T, 3-term bf16 split, fp32 accumulate.
// CTA = 128 rows x 64 cols. grid.x = 12 (z*4 + colblock), grid.y = 64 rowblocks.
// K = 256 in 4 chunks of 64, cp.async double-buffered.
// Smem rows: 64 bf16 = 128B data + 16B pad (stride 144), hi/lo in separate regions.
// ---------------------------------------------------------------------------
#define QX_H 0
#define QX_L 18432
#define QW_H 36864
#define QW_L 46080
#define QBUF 55296
#define QSMT (2 * QBUF)

__global__ __launch_bounds__(256, 2) void qkv_mma(void)
{
    extern __shared__ __align__(16) unsigned char qsm[];
    const uint32_t sb = smem_u32(qsm);

    const int tid  = threadIdx.x;
    const int w    = tid >> 5;
    const int lane = tid & 31;
    const int l4   = lane & 15;
    const int qd   = lane & 3;
    const int z    = blockIdx.x >> 2;
    const int n0   = (blockIdx.x & 3) * 64;
    const int row0 = blockIdx.y * 128;

    const __nv_bfloat16* Wh = g_wh[z];
    const __nv_bfloat16* Wl = g_wl[z];

    auto stage = [&](int k0, uint32_t buf) {
        // x tile: 128 rows x 64 cols, hi + lo = 2048 16B chunks
        #pragma unroll
        for (int i = 0; i < 8; i++) {
            int idx = i * 256 + tid;
            int isLo = idx >> 10;
            int rem  = idx & 1023;
            int r = rem >> 3, c = rem & 7;
            const __nv_bfloat16* src = (isLo ? g_xl : g_xh) + (size_t)(row0 + r) * HIDDEN + k0 + c * 8;
            cp16(sb + buf + (isLo ? QX_L : QX_H) + r * 144 + c * 16, src);
        }
        // W tile: 64 rows x 64 cols, hi + lo = 1024 chunks
        #pragma unroll
        for (int i = 0; i < 4; i++) {
            int idx = i * 256 + tid;
            int isLo = idx >> 9;
            int rem  = idx & 511;
            int r = rem >> 3, c = rem & 7;
            const __nv_bfloat16* src = (isLo ? Wl : Wh) + (size_t)(n0 + r) * HIDDEN + k0 + c * 8;
            cp16(sb + buf + (isLo ? QW_L : QW_H) + r * 144 + c * 16, src);
        }
    };

    float oacc[8][4] = {};

    stage(0, 0);
    CP_COMMIT();

    for (int it = 0; it < 4; it++) {
        const uint32_t buf = (it & 1) ? QBUF : 0;
        CP_WAIT0();
        __syncthreads();
        if (it < 3) {
            stage((it + 1) * 64, (it & 1) ? 0 : QBUF);
            CP_COMMIT();
        }

        const uint32_t axh = sb + buf + QX_H + (16 * w + l4) * 144 + ((lane >> 4) & 1) * 16;
        const uint32_t axl = sb + buf + QX_L + (16 * w + l4) * 144 + ((lane >> 4) & 1) * 16;
        const uint32_t bwh = sb + buf + QW_H + (l4 & 7) * 144 + ((l4 >> 3) & 1) * 16;
        const uint32_t bwl = sb + buf + QW_L + (l4 & 7) * 144 + ((l4 >> 3) & 1) * 16;

        #pragma unroll
        for (int s = 0; s < 4; s++) {
            uint32_t ah[4], al[4];
            ldsm_x4(ah, axh + s * 32);
            ldsm_x4(al, axl + s * 32);
            #pragma unroll
            for (int j = 0; j < 8; j++) {
                uint32_t bh0, bh1, bl0, bl1;
                ldsm_x2(bh0, bh1, bwh + s * 32 + j * (8 * 144));
                ldsm_x2(bl0, bl1, bwl + s * 32 + j * (8 * 144));
                mma16816(oacc[j], ah, bh0, bh1);   // xhi . whi
                mma16816(oacc[j], al, bh0, bh1);   // xlo . whi
                mma16816(oacc[j], ah, bl0, bl1);   // xhi . wlo
            }
        }
        __syncthreads();
    }

    // ---- epilogue: fp32 -> bf16 hi/lo, store to g_hi/g_lo[z] ----
    {
        const int r0 = row0 + 16 * w + (lane >> 2);
        __nv_bfloat16* dh = g_hi[z];
        __nv_bfloat16* dl = g_lo[z];
        #pragma unroll
        for (int j = 0; j < 8; j++) {
            const int col = n0 + 8 * j + qd * 2;
            // row r0
            uint32_t hp = packbf(oacc[j][0], oacc[j][1]);
            float f0 = __uint_as_float(hp << 16);
            float f1 = __uint_as_float(hp & 0xFFFF0000u);
            uint32_t lp = packbf(oacc[j][0] - f0, oacc[j][1] - f1);
            *(uint32_t*)(dh + (size_t)r0 * HIDDEN + col) = hp;
            *(uint32_t*)(dl + (size_t)r0 * HIDDEN + col) = lp;
            // row r0 + 8
            hp = packbf(oacc[j][2], oacc[j][3]);
            f0 = __uint_as_float(hp << 16);
            f1 = __uint_as_float(hp & 0xFFFF0000u);
            lp = packbf(oacc[j][2] - f0, oacc[j][3] - f1);
            *(uint32_t*)(dh + (size_t)(r0 + 8) * HIDDEN + col) = hp;
            *(uint32_t*)(dl + (size_t)(r0 + 8) * HIDDEN + col) = lp;
        }
    }
}

// ---------------------------------------------------------------------------
// FA2-style attention, cp.async pipelined (unchanged from R6).
// ---------------------------------------------------------------------------
#define OQ    0
#define OKV0  18432
#define OKV1  36864
#define OADJ  55296
#define SMT   88064
#define KVOFS 9216

__global__ __launch_bounds__(256, 2) void attn_kernel(
    const float* __restrict__ x, float* __restrict__ out)
{
    extern __shared__ __align__(16) unsigned char sm[];
    const uint32_t sb = smem_u32(sm);

    const int tid  = threadIdx.x;
    const int w    = tid >> 5;
    const int lane = tid & 31;
    const int l4   = lane & 15;
    const int qd   = lane & 3;
    const int b = blockIdx.z, h = blockIdx.y;
    const int q0 = blockIdx.x * 128;

    const __nv_bfloat16* Qh = g_hi[0];
    const __nv_bfloat16* Ql = g_lo[0];
    const __nv_bfloat16* Kh = g_hi[1];
    const __nv_bfloat16* Kl = g_lo[1];
    const __nv_bfloat16* Vh = g_hi[2];
    const __nv_bfloat16* Vl = g_lo[2];

    auto stage_kv = [&](int kt, uint32_t obuf) {
        #pragma unroll
        for (int i = 0; i < 4; i++) {
            int idx = i * 256 + tid;
            int isV = idx >> 9;
            int r   = (idx >> 3) & 63;
            int c   = idx & 7;
            size_t g = (size_t)(b * NA + kt * 64 + r) * HIDDEN + h * HD;
            const __nv_bfloat16* hi = isV ? Vh : Kh;
            const __nv_bfloat16* lo = isV ? Vl : Kl;
            const char* src = (c < 4) ? (const char*)(hi + g) + c * 16
                                      : (const char*)(lo + g) + (c - 4) * 16;
            cp16(sb + obuf + isV * KVOFS + r * 144 + c * 16, src);
        }
    };
    auto stage_adjm = [&](int kt) {
        #pragma unroll
        for (int i = 0; i < 8; i++) {
            int idx = i * 256 + tid;
            int r   = idx >> 4;
            int c16 = idx & 15;
            int pc  = c16 ^ (2 * (r & 7));
            const float* src = g_adjm + ((size_t)(b * NA + q0 + r)) * NA + kt * 64 + c16 * 4;
            cp16(sb + OADJ + r * 256 + pc * 16, src);
        }
    };

    #pragma unroll
    for (int i = 0; i < 4; i++) {
        int idx = i * 256 + tid;
        int r = idx >> 3, c = idx & 7;
        size_t g = (size_t)(b * NA + q0 + r) * HIDDEN + h * HD;
        uint4 v = (c < 4) ? ((const uint4*)(Qh + g))[c] : ((const uint4*)(Ql + g))[c - 4];
        *(uint4*)(sm + OQ + r * 144 + c * 16) = v;
    }
    stage_kv(0, OKV0);
    CP_COMMIT();
    stage_adjm(0);
    CP_COMMIT();
    __syncthreads();

    uint32_t qf[2][2][4];
    {
        uint32_t base = sb + OQ + (16 * w + l4) * 144 + ((lane >> 4) & 1) * 16;
        #pragma unroll
        for (int p = 0; p < 2; p++)
            #pragma unroll
            for (int s = 0; s < 2; s++)
                ldsm_x4(qf[p][s], base + p * 64 + s * 32);
    }

    float m0 = -1e30f, m1 = -1e30f, l0 = 0.f, l1 = 0.f;
    float oacc[4][4] = {};

    const int rw = 16 * w + (lane >> 2);
    const int r7 = rw & 7;

    for (int kt = 0; kt < 8; kt++) {
        const uint32_t obuf = (kt & 1) ? OKV1 : OKV0;
        CP_WAIT0();
        __syncthreads();

        float sacc[8][4];
        #pragma unroll
        for (int j = 0; j < 8; j++)
            #pragma unroll
            for (int e = 0; e < 4; e++) sacc[j][e] = 0.f;

        #pragma unroll
        for (int t3 = 0; t3 < 3; t3++) {
            const int pq = (t3 == 1) ? 1 : 0;
            const int pk = (t3 == 2) ? 1 : 0;
            #pragma unroll
            for (int s = 0; s < 2; s++) {
                uint32_t kbase = sb + obuf + (l4 & 7) * 144 + pk * 64 + s * 32 + ((l4 >> 3) & 1) * 16;
                #pragma unroll
                for (int j = 0; j < 8; j++) {
                    uint32_t b0, b1;
                    ldsm_x2(b0, b1, kbase + j * (8 * 144));
                    mma16816(sacc[j], qf[pq][s], b0, b1);
                }
            }
        }

        const uint32_t arow = OADJ + rw * 256;
        float rmax0 = -1e30f, rmax1 = -1e30f;
        #pragma unroll
        for (int j = 0; j < 8; j++) {
            uint32_t off = (uint32_t)(((qd + 4 * j) ^ (4 * r7)) << 3);
            float2 a0 = *(const float2*)(sm + arow + off);
            float2 a1 = *(const float2*)(sm + arow + 8 * 256 + off);
            float s0 = fmaf(sacc[j][0], 0.125f, a0.x);
            float s1 = fmaf(sacc[j][1], 0.125f, a0.y);
            float s2 = fmaf(sacc[j][2], 0.125f, a1.x);
            float s3 = fmaf(sacc[j][3], 0.125f, a1.y);
            sacc[j][0] = s0; sacc[j][1] = s1; sacc[j][2] = s2; sacc[j][3] = s3;
            rmax0 = fmaxf(rmax0, fmaxf(s0, s1));
            rmax1 = fmaxf(rmax1, fmaxf(s2, s3));
        }
        #pragma unroll
        for (int o = 1; o <= 2; o <<= 1) {
            rmax0 = fmaxf(rmax0, __shfl_xor_sync(0xffffffffu, rmax0, o));
            rmax1 = fmaxf(rmax1, __shfl_xor_sync(0xffffffffu, rmax1, o));
        }

        const float mn0 = fmaxf(m0, rmax0), mn1 = fmaxf(m1, rmax1);
        const float corr0 = __expf(m0 - mn0), corr1 = __expf(m1 - mn1);
        m0 = mn0; m1 = mn1;

        uint32_t pf[2][4][4];
        float sum0 = 0.f, sum1 = 0.f;
        #pragma unroll
        for (int jp = 0; jp < 4; jp++) {
            float pv[2][4];
            #pragma unroll
            for (int half = 0; half < 2; half++) {
                int j = 2 * jp + half;
                float p0 = __expf(sacc[j][0] - mn0);
                float p1 = __expf(sacc[j][1] - mn0);
                float p2 = __expf(sacc[j][2] - mn1);
                float p3 = __expf(sacc[j][3] - mn1);
                sum0 += p0 + p1; sum1 += p2 + p3;
                pv[half][0] = p0; pv[half][1] = p1; pv[half][2] = p2; pv[half][3] = p3;
            }
            #pragma unroll
            for (int half = 0; half < 2; half++) {
                uint32_t hp01 = packbf(pv[half][0], pv[half][1]);
                uint32_t hp23 = packbf(pv[half][2], pv[half][3]);
                float h0 = __uint_as_float(hp01 << 16);
                float h1 = __uint_as_float(hp01 & 0xFFFF0000u);
                float h2 = __uint_as_float(hp23 << 16);
                float h3 = __uint_as_float(hp23 & 0xFFFF0000u);
                pf[0][jp][2 * half + 0] = hp01;
                pf[0][jp][2 * half + 1] = hp23;
                pf[1][jp][2 * half + 0] = packbf(pv[half][0] - h0, pv[half][1] - h1);
                pf[1][jp][2 * half + 1] = packbf(pv[half][2] - h2, pv[half][3] - h3);
            }
        }
        #pragma unroll
        for (int o = 1; o <= 2; o <<= 1) {
            sum0 += __shfl_xor_sync(0xffffffffu, sum0, o);
            sum1 += __shfl_xor_sync(0xffffffffu, sum1, o);
        }
        l0 = l0 * corr0 + sum0;
        l1 = l1 * corr1 + sum1;

        __syncthreads();
        if (kt < 7) {
            stage_kv(kt + 1, (kt & 1) ? OKV0 : OKV1);
            CP_COMMIT();
            stage_adjm(kt + 1);
            CP_COMMIT();
        }

        #pragma unroll
        for (int j = 0; j < 4; j++) {
            oacc[j][0] *= corr0; oacc[j][1] *= corr0;
            oacc[j][2] *= corr1; oacc[j][3] *= corr1;
        }
        #pragma unroll
        for (int t3 = 0; t3 < 3; t3++) {
            const int ph  = (t3 == 2) ? 1 : 0;
            const int pv_ = (t3 == 1) ? 1 : 0;
            #pragma unroll
            for (int s2 = 0; s2 < 4; s2++) {
                uint32_t vbase = sb + obuf + KVOFS + (16 * s2 + l4) * 144 + pv_ * 64;
                #pragma unroll
                for (int j = 0; j < 4; j++) {
                    uint32_t b0, b1;
                    ldsm_x2t(b0, b1, vbase + j * 16);
                    mma16816(oacc[j], pf[ph][s2], b0, b1);
                }
            }
        }
    }

    {
        const float inv0 = 1.0f / l0, inv1 = 1.0f / l1;
        const size_t g0 = ((size_t)b * NA + q0 + rw) * HIDDEN + h * HD + qd * 2;
        #pragma unroll
        for (int j = 0; j < 4; j++) {
            float2 x0 = *(const float2*)(x + g0 + 8 * j);
            float2 x1 = *(const float2*)(x + g0 + 8 * HIDDEN + 8 * j);
            float2 o0, o1;
            o0.x = fmaf(oacc[j][0], inv0, x0.x);
            o0.y = fmaf(oacc[j][1], inv0, x0.y);
            o1.x = fmaf(oacc[j][2], inv1, x1.x);
            o1.y = fmaf(oacc[j][3], inv1, x1.y);
            *(float2*)(out + g0 + 8 * j) = o0;
            *(float2*)(out + g0 + 8 * HIDDEN + 8 * j) = o1;
        }
    }
}

// ---------------------------------------------------------------------------
extern "C" void kernel_launch(void* const* d_in, const int* in_sizes, int n_in,
                              void* d_out, int out_size)
{
    const float* x    = (const float*)d_in[0];
    const int*   mask = (const int*)d_in[1];    // jax bool -> int32 in harness
    const float* adj  = (const float*)d_in[2];
    const float* Wq   = (const float*)d_in[3];
    const float* Wk   = (const float*)d_in[4];
    const float* Wv   = (const float*)d_in[5];
    float*       out  = (float*)d_out;

    adjm_kernel<<<NB * NA * NA / 1024, 256>>>(adj, mask);
    xsplit_kernel<<<NB * NA * HIDDEN / 1024, 256>>>(x);
    wsplit_kernel<<<dim3(HIDDEN * HIDDEN / 1024, 3), 256>>>(Wq, Wk, Wv);

    cudaFuncSetAttribute(qkv_mma, cudaFuncAttributeMaxDynamicSharedMemorySize, QSMT);
    qkv_mma<<<dim3(12, 64), 256, QSMT>>>();

    cudaFuncSetAttribute(attn_kernel, cudaFuncAttributeMaxDynamicSharedMemorySize, SMT);
    attn_kernel<<<dim3(NA / 128, NH, NB), 256, SMT>>>(x, out);
}

// round 8
// speedup vs baseline: 3.6787x; 1.0359x over previous
#include <cuda_runtime.h>
#include <cuda_bf16.h>
#include <cstdint>

#define NB 16
#define NA 512
#define NH 8
#define HD 32
#define HIDDEN 256

// bf16 hi/lo split Q/K/V, [row][hidden]. 0=Q 1=K 2=V.
__device__ __nv_bfloat16 g_hi[3][NB * NA * HIDDEN];
__device__ __nv_bfloat16 g_lo[3][NB * NA * HIDDEN];
// combined adjacency+mask: mask ? -1e30 : adj
__device__ float g_adjm[NB * NA * NA];
// bf16 hi/lo split of x and the three weight matrices
__device__ __nv_bfloat16 g_xh[NB * NA * HIDDEN];
__device__ __nv_bfloat16 g_xl[NB * NA * HIDDEN];
__device__ __nv_bfloat16 g_wh[3][HIDDEN * HIDDEN];
__device__ __nv_bfloat16 g_wl[3][HIDDEN * HIDDEN];

// ---------------------------------------------------------------------------
// helpers
// ---------------------------------------------------------------------------
__device__ __forceinline__ uint32_t smem_u32(const void* p) {
    uint32_t a;
    asm("{ .reg .u64 t; cvta.to.shared.u64 t, %1; cvt.u32.u64 %0, t; }" : "=r"(a) : "l"(p));
    return a;
}
__device__ __forceinline__ void ldsm_x4(uint32_t* r, uint32_t a) {
    asm volatile("ldmatrix.sync.aligned.m8n8.x4.shared.b16 {%0,%1,%2,%3}, [%4];"
                 : "=r"(r[0]), "=r"(r[1]), "=r"(r[2]), "=r"(r[3]) : "r"(a));
}
__device__ __forceinline__ void ldsm_x4t(uint32_t* r, uint32_t a) {
    asm volatile("ldmatrix.sync.aligned.m8n8.x4.trans.shared.b16 {%0,%1,%2,%3}, [%4];"
                 : "=r"(r[0]), "=r"(r[1]), "=r"(r[2]), "=r"(r[3]) : "r"(a));
}
__device__ __forceinline__ void mma16816(float* c, const uint32_t* a, uint32_t b0, uint32_t b1) {
    asm volatile("mma.sync.aligned.m16n8k16.row.col.f32.bf16.bf16.f32 "
                 "{%0,%1,%2,%3}, {%4,%5,%6,%7}, {%8,%9}, {%0,%1,%2,%3};"
                 : "+f"(c[0]), "+f"(c[1]), "+f"(c[2]), "+f"(c[3])
                 : "r"(a[0]), "r"(a[1]), "r"(a[2]), "r"(a[3]), "r"(b0), "r"(b1));
}
__device__ __forceinline__ void cp16(uint32_t s, const void* g) {
    asm volatile("cp.async.cg.shared.global [%0], [%1], 16;" :: "r"(s), "l"(g));
}
#define CP_COMMIT() asm volatile("cp.async.commit_group;" ::: "memory")
#define CP_WAIT0()  asm volatile("cp.async.wait_group 0;" ::: "memory")

// pack (a -> bits[15:0], b -> bits[31:16])
__device__ __forceinline__ uint32_t packbf(float a, float b) {
    uint32_t r;
    asm("cvt.rn.bf16x2.f32 %0, %1, %2;" : "=r"(r) : "f"(b), "f"(a));
    return r;
}

// ---------------------------------------------------------------------------
// prepro: adjm = mask ? -1e30 : adj
// ---------------------------------------------------------------------------
__global__ __launch_bounds__(256) void adjm_kernel(
    const float* __restrict__ adj, const int* __restrict__ mask)
{
    size_t i = ((size_t)blockIdx.x * 256 + threadIdx.x) * 4;
    float4 a = *(const float4*)(adj + i);
    int4   m = *(const int4*)(mask + i);
    if (m.x) a.x = -1e30f;
    if (m.y) a.y = -1e30f;
    if (m.z) a.z = -1e30f;
    if (m.w) a.w = -1e30f;
    *(float4*)(g_adjm + i) = a;
}

// ---------------------------------------------------------------------------
// prepro: fp32 -> bf16 hi/lo split (x and W)
// ---------------------------------------------------------------------------
__device__ __forceinline__ void split4(const float* src, __nv_bfloat16* dh,
                                       __nv_bfloat16* dl, size_t i)
{
    float4 v = *(const float4*)(src + i);
    uint32_t h0 = packbf(v.x, v.y);
    uint32_t h1 = packbf(v.z, v.w);
    float f0 = __uint_as_float(h0 << 16);
    float f1 = __uint_as_float(h0 & 0xFFFF0000u);
    float f2 = __uint_as_float(h1 << 16);
    float f3 = __uint_as_float(h1 & 0xFFFF0000u);
    uint32_t l0 = packbf(v.x - f0, v.y - f1);
    uint32_t l1 = packbf(v.z - f2, v.w - f3);
    *(uint2*)(dh + i) = make_uint2(h0, h1);
    *(uint2*)(dl + i) = make_uint2(l0, l1);
}
__global__ __launch_bounds__(256) void xsplit_kernel(const float* __restrict__ x)
{
    size_t i = ((size_t)blockIdx.x * 256 + threadIdx.x) * 4;
    split4(x, g_xh, g_xl, i);
}
__global__ __launch_bounds__(256) void wsplit_kernel(
    const float* __restrict__ Wq, const float* __restrict__ Wk,
    const float* __restrict__ Wv)
{
    const int z = blockIdx.y;
    const float* W = (z == 0) ? Wq : (z == 1) ? Wk : Wv;
    size_t i = ((size_t)blockIdx.x * 256 + threadIdx.x) * 4;
    split4(W, g_wh[z], g_wl[z], i);
}

// ---------------------------------------------------------------------------
// QKV projection on HMMA (3-term bf16 split). CTA = 128 rows x 64 cols.
// ---------------------------------------------------------------------------
#define QX_H 0
#define QX_L 18432
#define QW_H 36864
#define QW_L 46080
#define QBUF 55296
#define QSMT (2 * QBUF)

__global__ __launch_bounds__(256, 2) void qkv_mma(void)
{
    extern __shared__ __align__(16) unsigned char qsm[];
    const uint32_t sb = smem_u32(qsm);

    const int tid  = threadIdx.x;
    const int w    = tid >> 5;
    const int lane = tid & 31;
    const int l4   = lane & 15;
    const int qd   = lane & 3;
    const int z    = blockIdx.x >> 2;
    const int n0   = (blockIdx.x & 3) * 64;
    const int row0 = blockIdx.y * 128;

    const __nv_bfloat16* Wh = g_wh[z];
    const __nv_bfloat16* Wl = g_wl[z];

    auto stage = [&](int k0, uint32_t buf) {
        #pragma unroll
        for (int i = 0; i < 8; i++) {
            int idx = i * 256 + tid;
            int isLo = idx >> 10;
            int rem  = idx & 1023;
            int r = rem >> 3, c = rem & 7;
            const __nv_bfloat16* src = (isLo ? g_xl : g_xh) + (size_t)(row0 + r) * HIDDEN + k0 + c * 8;
            cp16(sb + buf + (isLo ? QX_L : QX_H) + r * 144 + c * 16, src);
        }
        #pragma unroll
        for (int i = 0; i < 4; i++) {
            int idx = i * 256 + tid;
            int isLo = idx >> 9;
            int rem  = idx & 511;
            int r = rem >> 3, c = rem & 7;
            const __nv_bfloat16* src = (isLo ? Wl : Wh) + (size_t)(n0 + r) * HIDDEN + k0 + c * 8;
            cp16(sb + buf + (isLo ? QW_L : QW_H) + r * 144 + c * 16, src);
        }
    };

    float oacc[8][4] = {};

    stage(0, 0);
    CP_COMMIT();

    for (int it = 0; it < 4; it++) {
        const uint32_t buf = (it & 1) ? QBUF : 0;
        CP_WAIT0();
        __syncthreads();
        if (it < 3) {
            stage((it + 1) * 64, (it & 1) ? 0 : QBUF);
            CP_COMMIT();
        }

        const uint32_t axh = sb + buf + QX_H + (16 * w + l4) * 144 + ((lane >> 4) & 1) * 16;
        const uint32_t axl = sb + buf + QX_L + (16 * w + l4) * 144 + ((lane >> 4) & 1) * 16;
        const uint32_t bwh = sb + buf + QW_H + (l4 & 7) * 144 + ((l4 >> 3) & 1) * 16 + (lane >> 4) * (8 * 144);
        const uint32_t bwl = sb + buf + QW_L + (l4 & 7) * 144 + ((l4 >> 3) & 1) * 16 + (lane >> 4) * (8 * 144);

        #pragma unroll
        for (int s = 0; s < 4; s++) {
            uint32_t ah[4], al[4];
            ldsm_x4(ah, axh + s * 32);
            ldsm_x4(al, axl + s * 32);
            #pragma unroll
            for (int jp = 0; jp < 4; jp++) {
                uint32_t rh[4], rl[4];
                ldsm_x4(rh, bwh + s * 32 + jp * (16 * 144));
                ldsm_x4(rl, bwl + s * 32 + jp * (16 * 144));
                mma16816(oacc[2*jp],   ah, rh[0], rh[1]);
                mma16816(oacc[2*jp],   al, rh[0], rh[1]);
                mma16816(oacc[2*jp],   ah, rl[0], rl[1]);
                mma16816(oacc[2*jp+1], ah, rh[2], rh[3]);
                mma16816(oacc[2*jp+1], al, rh[2], rh[3]);
                mma16816(oacc[2*jp+1], ah, rl[2], rl[3]);
            }
        }
        __syncthreads();
    }

    // ---- epilogue: fp32 -> bf16 hi/lo, store to g_hi/g_lo[z] ----
    {
        const int r0 = row0 + 16 * w + (lane >> 2);
        __nv_bfloat16* dh = g_hi[z];
        __nv_bfloat16* dl = g_lo[z];
        #pragma unroll
        for (int j = 0; j < 8; j++) {
            const int col = n0 + 8 * j + qd * 2;
            uint32_t hp = packbf(oacc[j][0], oacc[j][1]);
            float f0 = __uint_as_float(hp << 16);
            float f1 = __uint_as_float(hp & 0xFFFF0000u);
            uint32_t lp = packbf(oacc[j][0] - f0, oacc[j][1] - f1);
            *(uint32_t*)(dh + (size_t)r0 * HIDDEN + col) = hp;
            *(uint32_t*)(dl + (size_t)r0 * HIDDEN + col) = lp;
            hp = packbf(oacc[j][2], oacc[j][3]);
            f0 = __uint_as_float(hp << 16);
            f1 = __uint_as_float(hp & 0xFFFF0000u);
            lp = packbf(oacc[j][2] - f0, oacc[j][3] - f1);
            *(uint32_t*)(dh + (size_t)(r0 + 8) * HIDDEN + col) = hp;
            *(uint32_t*)(dl + (size_t)(r0 + 8) * HIDDEN + col) = lp;
        }
    }
}

// ---------------------------------------------------------------------------
// FA2-style attention: cp.async KV double-buffer, adjm via batched LDG,
// ldsm x4 B-operands. One __syncthreads per K-tile.
// ---------------------------------------------------------------------------
#define OQ    0
#define OKV0  18432
#define OKV1  36864
#define SMT   55296
#define KVOFS 9216

__global__ __launch_bounds__(256, 2) void attn_kernel(
    const float* __restrict__ x, float* __restrict__ out)
{
    extern __shared__ __align__(16) unsigned char sm[];
    const uint32_t sb = smem_u32(sm);

    const int tid  = threadIdx.x;
    const int w    = tid >> 5;
    const int lane = tid & 31;
    const int l4   = lane & 15;
    const int qd   = lane & 3;
    const int b = blockIdx.z, h = blockIdx.y;
    const int q0 = blockIdx.x * 128;

    const __nv_bfloat16* Qh = g_hi[0];
    const __nv_bfloat16* Ql = g_lo[0];
    const __nv_bfloat16* Kh = g_hi[1];
    const __nv_bfloat16* Kl = g_lo[1];
    const __nv_bfloat16* Vh = g_hi[2];
    const __nv_bfloat16* Vl = g_lo[2];

    auto stage_kv = [&](int kt, uint32_t obuf) {
        #pragma unroll
        for (int i = 0; i < 4; i++) {
            int idx = i * 256 + tid;
            int isV = idx >> 9;
            int r   = (idx >> 3) & 63;
            int c   = idx & 7;
            size_t g = (size_t)(b * NA + kt * 64 + r) * HIDDEN + h * HD;
            const __nv_bfloat16* hi = isV ? Vh : Kh;
            const __nv_bfloat16* lo = isV ? Vl : Kl;
            const char* src = (c < 4) ? (const char*)(hi + g) + c * 16
                                      : (const char*)(lo + g) + (c - 4) * 16;
            cp16(sb + obuf + isV * KVOFS + r * 144 + c * 16, src);
        }
    };

    // ---- stage Q ----
    #pragma unroll
    for (int i = 0; i < 4; i++) {
        int idx = i * 256 + tid;
        int r = idx >> 3, c = idx & 7;
        size_t g = (size_t)(b * NA + q0 + r) * HIDDEN + h * HD;
        uint4 v = (c < 4) ? ((const uint4*)(Qh + g))[c] : ((const uint4*)(Ql + g))[c - 4];
        *(uint4*)(sm + OQ + r * 144 + c * 16) = v;
    }
    stage_kv(0, OKV0);
    CP_COMMIT();
    __syncthreads();

    uint32_t qf[2][2][4];
    {
        uint32_t base = sb + OQ + (16 * w + l4) * 144 + ((lane >> 4) & 1) * 16;
        #pragma unroll
        for (int p = 0; p < 2; p++)
            #pragma unroll
            for (int s = 0; s < 2; s++)
                ldsm_x4(qf[p][s], base + p * 64 + s * 32);
    }

    float m0 = -1e30f, m1 = -1e30f, l0 = 0.f, l1 = 0.f;
    float oacc[4][4] = {};

    const int rw = 16 * w + (lane >> 2);
    const float* adjp = g_adjm + ((size_t)(b * NA + q0 + rw)) * NA + qd * 2;

    for (int kt = 0; kt < 8; kt++) {
        const uint32_t obuf = (kt & 1) ? OKV1 : OKV0;
        CP_WAIT0();
        __syncthreads();                          // KV[kt] visible; prev iter done
        if (kt < 7) {                             // prefetch next KV immediately
            stage_kv(kt + 1, (kt & 1) ? OKV0 : OKV1);
            CP_COMMIT();
        }

        // ---- S = QK^T : 3 terms x 2 k16 x 4 jp (x4 B loads) ----
        float sacc[8][4];
        #pragma unroll
        for (int j = 0; j < 8; j++)
            #pragma unroll
            for (int e = 0; e < 4; e++) sacc[j][e] = 0.f;

        #pragma unroll
        for (int t3 = 0; t3 < 3; t3++) {
            const int pq = (t3 == 1) ? 1 : 0;
            const int pk = (t3 == 2) ? 1 : 0;
            #pragma unroll
            for (int s = 0; s < 2; s++) {
                uint32_t kb = sb + obuf + (l4 & 7) * 144 + pk * 64 + s * 32
                            + ((l4 >> 3) & 1) * 16 + (lane >> 4) * (8 * 144);
                #pragma unroll
                for (int jp = 0; jp < 4; jp++) {
                    uint32_t r[4];
                    ldsm_x4(r, kb + jp * (16 * 144));
                    mma16816(sacc[2*jp],   qf[pq][s], r[0], r[1]);
                    mma16816(sacc[2*jp+1], qf[pq][s], r[2], r[3]);
                }
            }
        }

        // ---- scores: adjm via gmem (masked already -1e30) ----
        const float* ab = adjp + kt * 64;
        float rmax0 = -1e30f, rmax1 = -1e30f;
        #pragma unroll
        for (int j = 0; j < 8; j++) {
            float2 a0 = *(const float2*)(ab + 8 * j);
            float2 a1 = *(const float2*)(ab + 8 * NA + 8 * j);
            float s0 = fmaf(sacc[j][0], 0.125f, a0.x);
            float s1 = fmaf(sacc[j][1], 0.125f, a0.y);
            float s2 = fmaf(sacc[j][2], 0.125f, a1.x);
            float s3 = fmaf(sacc[j][3], 0.125f, a1.y);
            sacc[j][0] = s0; sacc[j][1] = s1; sacc[j][2] = s2; sacc[j][3] = s3;
            rmax0 = fmaxf(rmax0, fmaxf(s0, s1));
            rmax1 = fmaxf(rmax1, fmaxf(s2, s3));
        }
        #pragma unroll
        for (int o = 1; o <= 2; o <<= 1) {
            rmax0 = fmaxf(rmax0, __shfl_xor_sync(0xffffffffu, rmax0, o));
            rmax1 = fmaxf(rmax1, __shfl_xor_sync(0xffffffffu, rmax1, o));
        }

        const float mn0 = fmaxf(m0, rmax0), mn1 = fmaxf(m1, rmax1);
        const float corr0 = __expf(m0 - mn0), corr1 = __expf(m1 - mn1);
        m0 = mn0; m1 = mn1;

        uint32_t pf[2][4][4];
        float sum0 = 0.f, sum1 = 0.f;
        #pragma unroll
        for (int jp = 0; jp < 4; jp++) {
            float pv[2][4];
            #pragma unroll
            for (int half = 0; half < 2; half++) {
                int j = 2 * jp + half;
                float p0 = __expf(sacc[j][0] - mn0);
                float p1 = __expf(sacc[j][1] - mn0);
                float p2 = __expf(sacc[j][2] - mn1);
                float p3 = __expf(sacc[j][3] - mn1);
                sum0 += p0 + p1; sum1 += p2 + p3;
                pv[half][0] = p0; pv[half][1] = p1; pv[half][2] = p2; pv[half][3] = p3;
            }
            #pragma unroll
            for (int half = 0; half < 2; half++) {
                uint32_t hp01 = packbf(pv[half][0], pv[half][1]);
                uint32_t hp23 = packbf(pv[half][2], pv[half][3]);
                float h0 = __uint_as_float(hp01 << 16);
                float h1 = __uint_as_float(hp01 & 0xFFFF0000u);
                float h2 = __uint_as_float(hp23 << 16);
                float h3 = __uint_as_float(hp23 & 0xFFFF0000u);
                pf[0][jp][2 * half + 0] = hp01;
                pf[0][jp][2 * half + 1] = hp23;
                pf[1][jp][2 * half + 0] = packbf(pv[half][0] - h0, pv[half][1] - h1);
                pf[1][jp][2 * half + 1] = packbf(pv[half][2] - h2, pv[half][3] - h3);
            }
        }
        #pragma unroll
        for (int o = 1; o <= 2; o <<= 1) {
            sum0 += __shfl_xor_sync(0xffffffffu, sum0, o);
            sum1 += __shfl_xor_sync(0xffffffffu, sum1, o);
        }
        l0 = l0 * corr0 + sum0;
        l1 = l1 * corr1 + sum1;

        // ---- rescale O, then O += P V (x4 trans loads) ----
        #pragma unroll
        for (int j = 0; j < 4; j++) {
            oacc[j][0] *= corr0; oacc[j][1] *= corr0;
            oacc[j][2] *= corr1; oacc[j][3] *= corr1;
        }
        #pragma unroll
        for (int t3 = 0; t3 < 3; t3++) {
            const int ph  = (t3 == 2) ? 1 : 0;
            const int pv_ = (t3 == 1) ? 1 : 0;
            #pragma unroll
            for (int s2 = 0; s2 < 4; s2++) {
                uint32_t vb = sb + obuf + KVOFS + (16 * s2 + l4) * 144 + pv_ * 64
                            + (lane >> 4) * 16;
                #pragma unroll
                for (int jp = 0; jp < 2; jp++) {
                    uint32_t r[4];
                    ldsm_x4t(r, vb + jp * 32);
                    mma16816(oacc[2*jp],   pf[ph][s2], r[0], r[1]);
                    mma16816(oacc[2*jp+1], pf[ph][s2], r[2], r[3]);
                }
            }
        }
    }

    // ---- finalize: /l + residual ----
    {
        const float inv0 = 1.0f / l0, inv1 = 1.0f / l1;
        const size_t g0 = ((size_t)b * NA + q0 + rw) * HIDDEN + h * HD + qd * 2;
        #pragma unroll
        for (int j = 0; j < 4; j++) {
            float2 x0 = *(const float2*)(x + g0 + 8 * j);
            float2 x1 = *(const float2*)(x + g0 + 8 * HIDDEN + 8 * j);
            float2 o0, o1;
            o0.x = fmaf(oacc[j][0], inv0, x0.x);
            o0.y = fmaf(oacc[j][1], inv0, x0.y);
            o1.x = fmaf(oacc[j][2], inv1, x1.x);
            o1.y = fmaf(oacc[j][3], inv1, x1.y);
            *(float2*)(out + g0 + 8 * j) = o0;
            *(float2*)(out + g0 + 8 * HIDDEN + 8 * j) = o1;
        }
    }
}

// ---------------------------------------------------------------------------
extern "C" void kernel_launch(void* const* d_in, const int* in_sizes, int n_in,
                              void* d_out, int out_size)
{
    const float* x    = (const float*)d_in[0];
    const int*   mask = (const int*)d_in[1];    // jax bool -> int32 in harness
    const float* adj  = (const float*)d_in[2];
    const float* Wq   = (const float*)d_in[3];
    const float* Wk   = (const float*)d_in[4];
    const float* Wv   = (const float*)d_in[5];
    float*       out  = (float*)d_out;

    adjm_kernel<<<NB * NA * NA / 1024, 256>>>(adj, mask);
    xsplit_kernel<<<NB * NA * HIDDEN / 1024, 256>>>(x);
    wsplit_kernel<<<dim3(HIDDEN * HIDDEN / 1024, 3), 256>>>(Wq, Wk, Wv);

    cudaFuncSetAttribute(qkv_mma, cudaFuncAttributeMaxDynamicSharedMemorySize, QSMT);
    qkv_mma<<<dim3(12, 64), 256, QSMT>>>();

    cudaFuncSetAttribute(attn_kernel, cudaFuncAttributeMaxDynamicSharedMemorySize, SMT);
    attn_kernel<<<dim3(NA / 128, NH, NB), 256, SMT>>>(x, out);
}